// round 8
// baseline (speedup 1.0000x reference)
#include <cuda_runtime.h>
#include <cuda_fp16.h>
#include <cstdint>

#define S_LEN 2048
#define NB 2
#define NH 16
#define DK 64
#define DM 1024
#define MROWS (NB * S_LEN)   // 4096
#define HEADELEMS ((size_t)NB * NH * S_LEN * DK)

// ---------------- scratch (__device__ globals; no allocs allowed) ----------
__device__ __half g_inqh[(size_t)MROWS * DM], g_inql[(size_t)MROWS * DM];
__device__ __half g_inkh[(size_t)MROWS * DM], g_inkl[(size_t)MROWS * DM];
__device__ __half g_invh[(size_t)MROWS * DM], g_invl[(size_t)MROWS * DM];
__device__ __half g_qh[HEADELEMS], g_ql[HEADELEMS];      // Q pair
__device__ __half g_kh[HEADELEMS];                       // K hi only
__device__ __half g_vth[HEADELEMS];                      // V^T hi only [b,h][d][t]
__device__ __half g_ath[(size_t)MROWS * DM], g_atl[(size_t)MROWS * DM];
__device__ __half g_wq[DM * DM], g_wk[DM * DM], g_wv[DM * DM], g_wo[DM * DM];

// ---------------- PTX helpers (all valid on non-'a' compute_103) -----------
__device__ __forceinline__ uint32_t smem_u32(const void* p) {
    uint32_t a;
    asm("{ .reg .u64 t; cvta.to.shared.u64 t, %1; cvt.u32.u64 %0, t; }" : "=r"(a) : "l"(p));
    return a;
}
#define CP16(dst, src) asm volatile("cp.async.ca.shared.global [%0], [%1], 16;" :: "r"(dst), "l"(src))
#define CPCOMMIT()     asm volatile("cp.async.commit_group;" ::: "memory")
#define CPWAIT1()      asm volatile("cp.async.wait_group 1;" ::: "memory")
#define CPWAIT0()      asm volatile("cp.async.wait_group 0;" ::: "memory")

__device__ __forceinline__ void ldsm4(uint32_t* r, uint32_t a) {
    asm volatile("ldmatrix.sync.aligned.m8n8.x4.shared.b16 {%0,%1,%2,%3}, [%4];"
                 : "=r"(r[0]), "=r"(r[1]), "=r"(r[2]), "=r"(r[3]) : "r"(a));
}
__device__ __forceinline__ void ldsm2(uint32_t* r, uint32_t a) {
    asm volatile("ldmatrix.sync.aligned.m8n8.x2.shared.b16 {%0,%1}, [%2];"
                 : "=r"(r[0]), "=r"(r[1]) : "r"(a));
}
// fp32-accumulator HMMA (hi terms)
__device__ __forceinline__ void mma16816(float* d, const uint32_t* a, const uint32_t* b) {
    asm volatile("mma.sync.aligned.m16n8k16.row.col.f32.f16.f16.f32 "
                 "{%0,%1,%2,%3},{%4,%5,%6,%7},{%8,%9},{%0,%1,%2,%3};"
                 : "+f"(d[0]), "+f"(d[1]), "+f"(d[2]), "+f"(d[3])
                 : "r"(a[0]), "r"(a[1]), "r"(a[2]), "r"(a[3]), "r"(b[0]), "r"(b[1]));
}
// fp16-accumulator HMMA (lo terms; d = 2x packed half2, same element->lane map)
__device__ __forceinline__ void mma16816h(uint32_t* d, const uint32_t* a, const uint32_t* b) {
    asm volatile("mma.sync.aligned.m16n8k16.row.col.f16.f16.f16.f16 "
                 "{%0,%1},{%2,%3,%4,%5},{%6,%7},{%0,%1};"
                 : "+r"(d[0]), "+r"(d[1])
                 : "r"(a[0]), "r"(a[1]), "r"(a[2]), "r"(a[3]), "r"(b[0]), "r"(b[1]));
}
__device__ __forceinline__ float2 h2f2(uint32_t u) {
    __half2 h = *reinterpret_cast<__half2*>(&u);
    return __half22float2(h);
}

// ---------------- fp16 split helpers ---------------------------------------
__device__ __forceinline__ void splitf(float x, uint16_t& h, uint16_t& l) {
    __half hh = __float2half_rn(x);
    float hf = __half2float(hh);
    __half ll = __float2half_rn(x - hf);
    h = __half_as_ushort(hh);
    l = __half_as_ushort(ll);
}
__device__ __forceinline__ uint32_t pack2(uint16_t a, uint16_t b) {
    return (uint32_t)a | ((uint32_t)b << 16);
}
__device__ __forceinline__ void psplit2(float x, float y, uint32_t& h, uint32_t& l) {
    uint16_t hx, lx, hy, ly;
    splitf(x, hx, lx); splitf(y, hy, ly);
    h = pack2(hx, hy); l = pack2(lx, ly);
}

// ---------------------------------------------------------------------------
// Elementwise split: fp32 -> fp16 hi/lo (same layout)
// ---------------------------------------------------------------------------
__global__ __launch_bounds__(256) void split_kernel(
    const float* __restrict__ x, __half* __restrict__ h, __half* __restrict__ l)
{
    const size_t i = (size_t)blockIdx.x * 256 + threadIdx.x;   // float4 index
    float4 v = ((const float4*)x)[i];
    uint32_t h0, l0, h1, l1;
    psplit2(v.x, v.y, h0, l0);
    psplit2(v.z, v.w, h1, l1);
    ((uint2*)h)[i] = make_uint2(h0, h1);
    ((uint2*)l)[i] = make_uint2(l0, l1);
}

// ---------------------------------------------------------------------------
// Weight transpose (fp16 hi only):  T[n][k] = fp16(W[k][n])
// ---------------------------------------------------------------------------
__global__ __launch_bounds__(256) void wsplit_kernel(
    const float* __restrict__ W, __half* __restrict__ Th)
{
    __shared__ float ts[32][33];
    const int tid = threadIdx.x;
    const int tx = tid & 31, ty = tid >> 5;                 // ty: 0..7
    const int k0 = blockIdx.x * 32, n0 = blockIdx.y * 32;
#pragma unroll
    for (int p = 0; p < 4; p++)
        ts[ty + 8 * p][tx] = W[(size_t)(k0 + ty + 8 * p) * DM + n0 + tx];
    __syncthreads();
#pragma unroll
    for (int p = 0; p < 4; p++) {
        const int r = ty + 8 * p;                            // local n
        Th[(size_t)(n0 + r) * DM + k0 + tx] = __float2half_rn(ts[tx][r]);
    }
}

// ---------------------------------------------------------------------------
// mma.sync GEMM: C[4096,1024] = A @ W^T + bias, fp16 split-2 (A pair, W hi)
// Hi term: fp32-acc HMMA.  Lo term (Al*Bh): fp16-acc HMMA (magnitudes ~2^-11).
// CTA 256 thr (8 warps, 2x4), tile 128x128, K-chunk 32, cp.async 2-stage.
// ---------------------------------------------------------------------------
#define GP 40                   // padded row stride (elements); 80B rows: conflict-free
#define G_STAGE (128 * GP * 2)  // 10240 bytes
#define G_SMEM  (6 * G_STAGE)   // 61440

__global__ __launch_bounds__(256, 2) void gemm_mma_kernel(
    const __half* __restrict__ Ah, const __half* __restrict__ Al,
    const __half* __restrict__ Bh, const float* __restrict__ bias,
    __half* __restrict__ Oh, __half* __restrict__ Ol,
    float* __restrict__ Of, int mode)
{
    extern __shared__ char smc[];
    const uint32_t smb = smem_u32(smc);
    const int tid = threadIdx.x, lane = tid & 31, wid = tid >> 5;
    const int m0 = blockIdx.y * 128, n0 = blockIdx.x * 128;
    const int wm = (wid >> 2) * 64, wn = (wid & 3) * 32;
    const uint32_t SAH = smb, SAL = smb + 2 * G_STAGE, SBH = smb + 4 * G_STAGE;

    // loader: tile = 128 rows x 64B (4 x16B). 512 segs/buffer -> 2 per thread.
#pragma unroll
    for (int p = 0; p < 2; p++) {
        const int idx = tid + p * 256, r = idx >> 2, c = idx & 3;
        const uint32_t d = (uint32_t)r * 80u + (uint32_t)c * 16u;
        const size_t ao = (size_t)(m0 + r) * DM + c * 8;
        const size_t bo = (size_t)(n0 + r) * DM + c * 8;
        CP16(SAH + d, Ah + ao); CP16(SAL + d, Al + ao); CP16(SBH + d, Bh + bo);
    }
    CPCOMMIT();

    float acc[4][4][4];
    uint32_t accl[4][4][2];
#pragma unroll
    for (int a = 0; a < 4; a++)
#pragma unroll
        for (int b = 0; b < 4; b++) {
#pragma unroll
            for (int c = 0; c < 4; c++) acc[a][b][c] = 0.f;
            accl[a][b][0] = 0u; accl[a][b][1] = 0u;
        }

    for (int ch = 0; ch < 32; ch++) {
        if (ch + 1 < 32) {
            const int k0 = (ch + 1) * 32;
            const uint32_t so = (uint32_t)((ch + 1) & 1) * G_STAGE;
#pragma unroll
            for (int p = 0; p < 2; p++) {
                const int idx = tid + p * 256, r = idx >> 2, c = idx & 3;
                const uint32_t d = (uint32_t)r * 80u + (uint32_t)c * 16u + so;
                const size_t ao = (size_t)(m0 + r) * DM + k0 + c * 8;
                const size_t bo = (size_t)(n0 + r) * DM + k0 + c * 8;
                CP16(SAH + d, Ah + ao); CP16(SAL + d, Al + ao); CP16(SBH + d, Bh + bo);
            }
            CPCOMMIT();
            CPWAIT1();
        } else {
            CPWAIT0();
        }
        __syncthreads();
        const uint32_t so = (uint32_t)(ch & 1) * G_STAGE;
#pragma unroll
        for (int ks = 0; ks < 2; ks++) {
            uint32_t ah[4][4], al[4][4], bh[4][2];
            const uint32_t aoff = (uint32_t)((lane & 15) * 80 +
                                  (ks * 16 + (lane >> 4) * 8) * 2) + so;
#pragma unroll
            for (int mb = 0; mb < 4; mb++) {
                const uint32_t ro = (uint32_t)(wm + mb * 16) * 80u;
                ldsm4(ah[mb], SAH + ro + aoff);
                ldsm4(al[mb], SAL + ro + aoff);
            }
            const uint32_t boff = (uint32_t)((lane & 7) * 80 +
                                  (ks * 16 + ((lane >> 3) & 1) * 8) * 2) + so;
#pragma unroll
            for (int nb = 0; nb < 4; nb++) {
                const uint32_t ro = (uint32_t)(wn + nb * 8) * 80u;
                ldsm2(bh[nb], SBH + ro + boff);
            }
#pragma unroll
            for (int mb = 0; mb < 4; mb++)
#pragma unroll
                for (int nb = 0; nb < 4; nb++) {
                    mma16816(acc[mb][nb], ah[mb], bh[nb]);
                    mma16816h(accl[mb][nb], al[mb], bh[nb]);
                }
        }
        __syncthreads();
    }

    // epilogue (fold f16 lo accumulators)
    const int lr = lane >> 2, lc = (lane & 3) * 2;
    const float sc = (mode == 0) ? 0.125f : 1.0f;
#pragma unroll
    for (int mb = 0; mb < 4; mb++) {
#pragma unroll
        for (int nb = 0; nb < 4; nb++) {
            const int col = n0 + wn + nb * 8 + lc;
            const float b0 = bias[col], b1 = bias[col + 1];
            const float2 lo01 = h2f2(accl[mb][nb][0]);
            const float2 lo23 = h2f2(accl[mb][nb][1]);
#pragma unroll
            for (int half_ = 0; half_ < 2; half_++) {
                const int row = m0 + wm + mb * 16 + lr + 8 * half_;
                const float e0 = half_ ? lo23.x : lo01.x;
                const float e1 = half_ ? lo23.y : lo01.y;
                const float v0 = (acc[mb][nb][2 * half_] + e0 + b0) * sc;
                const float v1 = (acc[mb][nb][2 * half_ + 1] + e1 + b1) * sc;
                const int bb = row >> 11, ss = row & (S_LEN - 1);
                const int h = col >> 6, d = col & 63;
                if (mode == 0) {            // Q: fp16 pair, headlayout
                    uint32_t hh, ll;
                    psplit2(v0, v1, hh, ll);
                    const size_t base = (((size_t)(bb * NH + h) * S_LEN + ss) << 6) + d;
                    *(uint32_t*)(Oh + base) = hh;
                    *(uint32_t*)(Ol + base) = ll;
                } else if (mode == 1) {     // K: fp16 hi, headlayout
                    const size_t base = (((size_t)(bb * NH + h) * S_LEN + ss) << 6) + d;
                    *(uint32_t*)(Oh + base) =
                        pack2(__half_as_ushort(__float2half_rn(v0)),
                              __half_as_ushort(__float2half_rn(v1)));
                } else if (mode == 2) {     // V: fp16 hi, transposed
                    const size_t base = ((size_t)(bb * NH + h) * DK + d) * S_LEN + ss;
                    Oh[base] = __float2half_rn(v0);
                    Oh[base + S_LEN] = __float2half_rn(v1);
                } else {
                    *(float2*)(Of + (size_t)row * DM + col) = make_float2(v0, v1);
                }
            }
        }
    }
}

// ---------------------------------------------------------------------------
// mma.sync flash attention, fp16 split-2; lo terms use fp16-acc HMMA.
// No-max softmax (scores bounded, 1/8 folded in Q). CTA: 128 q-rows x (b,h),
// 256 thr (8 warps x 16 rows). KV chunks of 64, cp.async 2-stage.
// ---------------------------------------------------------------------------
#define AP 72                     // padded row stride (elements) = 144B: conflict-free
#define A_QBYTES (128 * AP * 2)   // 18432
#define A_STAGE  (64 * AP * 2)    // 9216
#define A_SMEM   (2 * A_QBYTES + 4 * A_STAGE)   // 73728

__global__ __launch_bounds__(256, 2) void attn_mma_kernel(
    const __half* __restrict__ Qh, const __half* __restrict__ Ql,
    const __half* __restrict__ Kh, const __half* __restrict__ Vth,
    __half* __restrict__ AOh, __half* __restrict__ AOl)
{
    extern __shared__ char smc[];
    const uint32_t smb = smem_u32(smc);
    const int tid = threadIdx.x, lane = tid & 31, wid = tid >> 5;
    const int bh = blockIdx.y;
    const int q0 = blockIdx.x * 128;
    const uint32_t SQH = smb, SQL = smb + A_QBYTES;
    const uint32_t SKH = SQL + A_QBYTES, SVH = SKH + 2 * A_STAGE;

    const size_t qbase = ((size_t)bh * S_LEN + q0) * DK;
    const size_t kbase = (size_t)bh * S_LEN * DK;
    const size_t vbase = (size_t)bh * DK * S_LEN;

    // prologue: Q pair (1024 segs each) + K,V chunk 0 (512 segs each)
    {
#pragma unroll
        for (int p = 0; p < 4; p++) {
            const int idx = tid + p * 256, r = idx >> 3, c = idx & 7;
            const uint32_t d = (uint32_t)r * 144u + (uint32_t)c * 16u;
            const size_t o = qbase + (size_t)r * DK + c * 8;
            CP16(SQH + d, Qh + o);
            CP16(SQL + d, Ql + o);
        }
#pragma unroll
        for (int p = 0; p < 2; p++) {
            const int idx = tid + p * 256, r = idx >> 3, c = idx & 7;
            const uint32_t d = (uint32_t)r * 144u + (uint32_t)c * 16u;
            CP16(SKH + d, Kh + kbase + (size_t)r * DK + c * 8);
            CP16(SVH + d, Vth + vbase + (size_t)r * S_LEN + c * 8);
        }
        CPCOMMIT();
    }

    const int r0 = wid * 16;
    float oacc[8][4];
    uint32_t oaccl[8][2];
    float lsum[2] = {0.f, 0.f};
#pragma unroll
    for (int db = 0; db < 8; db++) {
#pragma unroll
        for (int e = 0; e < 4; e++) oacc[db][e] = 0.f;
        oaccl[db][0] = 0u; oaccl[db][1] = 0u;
    }

    for (int i = 0; i < 32; i++) {
        if (i + 1 < 32) {
            const int t0 = (i + 1) * 64;
            const uint32_t so = (uint32_t)((i + 1) & 1) * A_STAGE;
#pragma unroll
            for (int p = 0; p < 2; p++) {
                const int idx = tid + p * 256, r = idx >> 3, c = idx & 7;
                const uint32_t d = (uint32_t)r * 144u + (uint32_t)c * 16u + so;
                CP16(SKH + d, Kh + kbase + (size_t)(t0 + r) * DK + c * 8);
                CP16(SVH + d, Vth + vbase + (size_t)r * S_LEN + t0 + c * 8);
            }
            CPCOMMIT();
            CPWAIT1();
        } else {
            CPWAIT0();
        }
        __syncthreads();
        const uint32_t so = (uint32_t)(i & 1) * A_STAGE;

        // ---- MMA1: S[16 x 64] = (Qh+Ql) @ Kh^T; lo term in fp16 acc ----
        float sacc[8][4];
        uint32_t saccl[8][2];
#pragma unroll
        for (int nb = 0; nb < 8; nb++) {
#pragma unroll
            for (int e = 0; e < 4; e++) sacc[nb][e] = 0.f;
            saccl[nb][0] = 0u; saccl[nb][1] = 0u;
        }
#pragma unroll
        for (int ks = 0; ks < 4; ks++) {
            uint32_t qfh[4], qfl[4];
            const uint32_t qa = (uint32_t)((r0 + (lane & 15)) * 144 +
                                 (ks * 16 + (lane >> 4) * 8) * 2);
            ldsm4(qfh, SQH + qa);
            ldsm4(qfl, SQL + qa);
            const uint32_t bo = (uint32_t)((lane & 7) * 144 +
                                 (ks * 16 + ((lane >> 3) & 1) * 8) * 2) + so;
#pragma unroll
            for (int nb = 0; nb < 8; nb++) {
                uint32_t kb[2];
                ldsm2(kb, SKH + (uint32_t)(nb * 8) * 144u + bo);
                mma16816(sacc[nb], qfh, kb);
                mma16816h(saccl[nb], qfl, kb);
            }
        }

        // ---- fold lo, exp + row-sum partials (no max subtraction) ----
#pragma unroll
        for (int nb = 0; nb < 8; nb++) {
            const float2 s01 = h2f2(saccl[nb][0]);
            const float2 s23 = h2f2(saccl[nb][1]);
            sacc[nb][0] += s01.x; sacc[nb][1] += s01.y;
            sacc[nb][2] += s23.x; sacc[nb][3] += s23.y;
#pragma unroll
            for (int e = 0; e < 4; e++) {
                const float p = __expf(sacc[nb][e]);
                lsum[e >> 1] += p;
                sacc[nb][e] = p;
            }
        }

        // ---- MMA2: O[16 x 64] += (Ph+Pl) @ Vh; lo term in fp16 acc ----
#pragma unroll
        for (int ts = 0; ts < 4; ts++) {
            uint32_t ph[4], pl[4];
            psplit2(sacc[2 * ts][0],     sacc[2 * ts][1],     ph[0], pl[0]);
            psplit2(sacc[2 * ts][2],     sacc[2 * ts][3],     ph[1], pl[1]);
            psplit2(sacc[2 * ts + 1][0], sacc[2 * ts + 1][1], ph[2], pl[2]);
            psplit2(sacc[2 * ts + 1][2], sacc[2 * ts + 1][3], ph[3], pl[3]);
            const uint32_t vo = (uint32_t)((lane & 7) * 144 +
                                 (ts * 16 + ((lane >> 3) & 1) * 8) * 2) + so;
#pragma unroll
            for (int db = 0; db < 8; db++) {
                uint32_t vb[2];
                ldsm2(vb, SVH + (uint32_t)(db * 8) * 144u + vo);
                mma16816(oacc[db], ph, vb);
                mma16816h(oaccl[db], pl, vb);
            }
        }
        __syncthreads();
    }

    // ---- row-sum reduction across the 4 lanes owning each row ----
#pragma unroll
    for (int e = 0; e < 2; e++) {
        lsum[e] += __shfl_xor_sync(0xffffffffu, lsum[e], 1);
        lsum[e] += __shfl_xor_sync(0xffffffffu, lsum[e], 2);
    }
    const float inv0 = 1.f / lsum[0], inv1 = 1.f / lsum[1];

    // ---- epilogue: fold O lo, att fp16 pair [b][s][h*64+d] ----
    const int bb = bh >> 4, hh = bh & 15;
    const int rowa = q0 + r0 + (lane >> 2);
#pragma unroll
    for (int db = 0; db < 8; db++) {
        const float2 o01 = h2f2(oaccl[db][0]);
        const float2 o23 = h2f2(oaccl[db][1]);
        const int col = hh * 64 + db * 8 + (lane & 3) * 2;
        uint32_t h0, l0, h1, l1;
        psplit2((oacc[db][0] + o01.x) * inv0, (oacc[db][1] + o01.y) * inv0, h0, l0);
        psplit2((oacc[db][2] + o23.x) * inv1, (oacc[db][3] + o23.y) * inv1, h1, l1);
        const size_t ba = ((size_t)bb * S_LEN + rowa) * DM + col;
        const size_t bb2 = ba + (size_t)8 * DM;
        *(uint32_t*)(AOh + ba) = h0;  *(uint32_t*)(AOl + ba) = l0;
        *(uint32_t*)(AOh + bb2) = h1; *(uint32_t*)(AOl + bb2) = l1;
    }
}

// ---------------------------------------------------------------------------
extern "C" void kernel_launch(void* const* d_in, const int* in_sizes, int n_in,
                              void* d_out, int out_size)
{
    const float* q  = (const float*)d_in[0];
    const float* k  = (const float*)d_in[1];
    const float* v  = (const float*)d_in[2];
    const float* Wq = (const float*)d_in[3];
    const float* bq = (const float*)d_in[4];
    const float* Wk = (const float*)d_in[5];
    const float* bk = (const float*)d_in[6];
    const float* Wv = (const float*)d_in[7];
    const float* bv = (const float*)d_in[8];
    const float* Wo = (const float*)d_in[9];
    const float* bo = (const float*)d_in[10];
    float* out = (float*)d_out;

    __half *inqh, *inql, *inkh, *inkl, *invh, *invl;
    __half *qh, *ql, *kh, *vth, *ath, *atl, *wq, *wk, *wv, *wo;
    cudaGetSymbolAddress((void**)&inqh, g_inqh); cudaGetSymbolAddress((void**)&inql, g_inql);
    cudaGetSymbolAddress((void**)&inkh, g_inkh); cudaGetSymbolAddress((void**)&inkl, g_inkl);
    cudaGetSymbolAddress((void**)&invh, g_invh); cudaGetSymbolAddress((void**)&invl, g_invl);
    cudaGetSymbolAddress((void**)&qh,  g_qh);  cudaGetSymbolAddress((void**)&ql,  g_ql);
    cudaGetSymbolAddress((void**)&kh,  g_kh);
    cudaGetSymbolAddress((void**)&vth, g_vth);
    cudaGetSymbolAddress((void**)&ath, g_ath); cudaGetSymbolAddress((void**)&atl, g_atl);
    cudaGetSymbolAddress((void**)&wq, g_wq); cudaGetSymbolAddress((void**)&wk, g_wk);
    cudaGetSymbolAddress((void**)&wv, g_wv); cudaGetSymbolAddress((void**)&wo, g_wo);

    cudaFuncSetAttribute(gemm_mma_kernel, cudaFuncAttributeMaxDynamicSharedMemorySize, G_SMEM);
    cudaFuncSetAttribute(attn_mma_kernel, cudaFuncAttributeMaxDynamicSharedMemorySize, A_SMEM);

    // input splits (fp32 -> fp16 hi/lo)
    const int nblk = (MROWS * DM / 4) / 256;   // 4096
    split_kernel<<<nblk, 256>>>(q, inqh, inql);
    split_kernel<<<nblk, 256>>>(k, inkh, inkl);
    split_kernel<<<nblk, 256>>>(v, invh, invl);

    // weight transpose (fp16 hi)
    dim3 wg(32, 32);
    wsplit_kernel<<<wg, 256>>>(Wq, wq);
    wsplit_kernel<<<wg, 256>>>(Wk, wk);
    wsplit_kernel<<<wg, 256>>>(Wv, wv);
    wsplit_kernel<<<wg, 256>>>(Wo, wo);

    // projections
    dim3 gg(DM / 128, MROWS / 128);
    gemm_mma_kernel<<<gg, 256, G_SMEM>>>(inqh, inql, wq, bq, qh, ql, nullptr, 0);
    gemm_mma_kernel<<<gg, 256, G_SMEM>>>(inkh, inkl, wk, bk, kh, nullptr, nullptr, 1);
    gemm_mma_kernel<<<gg, 256, G_SMEM>>>(invh, invl, wv, bv, vth, nullptr, nullptr, 2);

    // attention
    dim3 ga(S_LEN / 128, NB * NH);
    attn_mma_kernel<<<ga, 256, A_SMEM>>>(qh, ql, kh, vth, ath, atl);

    // output projection
    gemm_mma_kernel<<<gg, 256, G_SMEM>>>(ath, atl, wo, bo, nullptr, nullptr, out, 3);
}

// round 9
// speedup vs baseline: 1.6308x; 1.6308x over previous
#include <cuda_runtime.h>
#include <cuda_fp16.h>
#include <cstdint>

#define S_LEN 2048
#define NB 2
#define NH 16
#define DK 64
#define DM 1024
#define MROWS (NB * S_LEN)   // 4096
#define HEADELEMS ((size_t)NB * NH * S_LEN * DK)

// ---------------- scratch (__device__ globals; no allocs allowed) ----------
__device__ __half g_inq[(size_t)MROWS * DM];
__device__ __half g_ink[(size_t)MROWS * DM];
__device__ __half g_inv[(size_t)MROWS * DM];
__device__ __half g_q[HEADELEMS];                        // [b,h][t][d], 1/8 folded
__device__ __half g_k[HEADELEMS];                        // [b,h][t][d]
__device__ __half g_vt[HEADELEMS];                       // [b,h][d][t]
__device__ __half g_at[(size_t)MROWS * DM];              // attention out [b][s][h*64+d]
__device__ __half g_wq[DM * DM], g_wk[DM * DM], g_wv[DM * DM], g_wo[DM * DM];

// ---------------- PTX helpers (all valid on non-'a' compute_103) -----------
__device__ __forceinline__ uint32_t smem_u32(const void* p) {
    uint32_t a;
    asm("{ .reg .u64 t; cvta.to.shared.u64 t, %1; cvt.u32.u64 %0, t; }" : "=r"(a) : "l"(p));
    return a;
}
#define CP16(dst, src) asm volatile("cp.async.ca.shared.global [%0], [%1], 16;" :: "r"(dst), "l"(src))
#define CPCOMMIT()     asm volatile("cp.async.commit_group;" ::: "memory")
#define CPWAIT1()      asm volatile("cp.async.wait_group 1;" ::: "memory")
#define CPWAIT0()      asm volatile("cp.async.wait_group 0;" ::: "memory")

__device__ __forceinline__ void ldsm4(uint32_t* r, uint32_t a) {
    asm volatile("ldmatrix.sync.aligned.m8n8.x4.shared.b16 {%0,%1,%2,%3}, [%4];"
                 : "=r"(r[0]), "=r"(r[1]), "=r"(r[2]), "=r"(r[3]) : "r"(a));
}
__device__ __forceinline__ void ldsm2(uint32_t* r, uint32_t a) {
    asm volatile("ldmatrix.sync.aligned.m8n8.x2.shared.b16 {%0,%1}, [%2];"
                 : "=r"(r[0]), "=r"(r[1]) : "r"(a));
}
__device__ __forceinline__ void mma16816(float* d, const uint32_t* a, const uint32_t* b) {
    asm volatile("mma.sync.aligned.m16n8k16.row.col.f32.f16.f16.f32 "
                 "{%0,%1,%2,%3},{%4,%5,%6,%7},{%8,%9},{%0,%1,%2,%3};"
                 : "+f"(d[0]), "+f"(d[1]), "+f"(d[2]), "+f"(d[3])
                 : "r"(a[0]), "r"(a[1]), "r"(a[2]), "r"(a[3]), "r"(b[0]), "r"(b[1]));
}

__device__ __forceinline__ uint32_t pack2(uint16_t a, uint16_t b) {
    return (uint32_t)a | ((uint32_t)b << 16);
}
__device__ __forceinline__ uint32_t pcvt2(float x, float y) {
    return pack2(__half_as_ushort(__float2half_rn(x)),
                 __half_as_ushort(__float2half_rn(y)));
}

// ---------------------------------------------------------------------------
// Elementwise convert: fp32 -> fp16 (same layout)
// ---------------------------------------------------------------------------
__global__ __launch_bounds__(256) void cvt_kernel(
    const float* __restrict__ x, __half* __restrict__ h)
{
    const size_t i = (size_t)blockIdx.x * 256 + threadIdx.x;   // float4 index
    float4 v = ((const float4*)x)[i];
    ((uint2*)h)[i] = make_uint2(pcvt2(v.x, v.y), pcvt2(v.z, v.w));
}

// ---------------------------------------------------------------------------
// Weight transpose + convert:  T[n][k] = fp16(W[k][n])
// ---------------------------------------------------------------------------
__global__ __launch_bounds__(256) void wsplit_kernel(
    const float* __restrict__ W, __half* __restrict__ Th)
{
    __shared__ float ts[32][33];
    const int tid = threadIdx.x;
    const int tx = tid & 31, ty = tid >> 5;                 // ty: 0..7
    const int k0 = blockIdx.x * 32, n0 = blockIdx.y * 32;
#pragma unroll
    for (int p = 0; p < 4; p++)
        ts[ty + 8 * p][tx] = W[(size_t)(k0 + ty + 8 * p) * DM + n0 + tx];
    __syncthreads();
#pragma unroll
    for (int p = 0; p < 4; p++) {
        const int r = ty + 8 * p;                            // local n
        Th[(size_t)(n0 + r) * DM + k0 + tx] = __float2half_rn(ts[tx][r]);
    }
}

// ---------------------------------------------------------------------------
// mma.sync GEMM: C[4096,1024] = A @ W^T + bias, pure fp16 operands, fp32 acc.
// CTA 256 thr (8 warps, 2x4), tile 128x128, K-chunk 32, cp.async 2-stage.
// mode 0: -> fp16 headlayout [b,h][t][d], scale 1/8   (Q)
// mode 1: -> fp16 headlayout                          (K)
// mode 2: -> fp16 transposed  [b,h][d][t]             (V)
// mode 3: -> fp32 [m][n]                              (out proj)
// ---------------------------------------------------------------------------
#define GP 40                   // padded row stride (elements); 80B rows: conflict-free
#define G_STAGE (128 * GP * 2)  // 10240 bytes
#define G_SMEM  (4 * G_STAGE)   // 40960

__global__ __launch_bounds__(256, 2) void gemm_mma_kernel(
    const __half* __restrict__ Ah, const __half* __restrict__ Bh,
    const float* __restrict__ bias,
    __half* __restrict__ Oh, float* __restrict__ Of, int mode)
{
    extern __shared__ char smc[];
    const uint32_t smb = smem_u32(smc);
    const int tid = threadIdx.x, lane = tid & 31, wid = tid >> 5;
    const int m0 = blockIdx.y * 128, n0 = blockIdx.x * 128;
    const int wm = (wid >> 2) * 64, wn = (wid & 3) * 32;
    const uint32_t SAH = smb, SBH = smb + 2 * G_STAGE;

    // loader: tile = 128 rows x 64B (4 x16B). 512 segs/buffer -> 2 per thread.
#pragma unroll
    for (int p = 0; p < 2; p++) {
        const int idx = tid + p * 256, r = idx >> 2, c = idx & 3;
        const uint32_t d = (uint32_t)r * 80u + (uint32_t)c * 16u;
        CP16(SAH + d, Ah + (size_t)(m0 + r) * DM + c * 8);
        CP16(SBH + d, Bh + (size_t)(n0 + r) * DM + c * 8);
    }
    CPCOMMIT();

    float acc[4][4][4];
#pragma unroll
    for (int a = 0; a < 4; a++)
#pragma unroll
        for (int b = 0; b < 4; b++)
#pragma unroll
            for (int c = 0; c < 4; c++) acc[a][b][c] = 0.f;

    for (int ch = 0; ch < 32; ch++) {
        if (ch + 1 < 32) {
            const int k0 = (ch + 1) * 32;
            const uint32_t so = (uint32_t)((ch + 1) & 1) * G_STAGE;
#pragma unroll
            for (int p = 0; p < 2; p++) {
                const int idx = tid + p * 256, r = idx >> 2, c = idx & 3;
                const uint32_t d = (uint32_t)r * 80u + (uint32_t)c * 16u + so;
                CP16(SAH + d, Ah + (size_t)(m0 + r) * DM + k0 + c * 8);
                CP16(SBH + d, Bh + (size_t)(n0 + r) * DM + k0 + c * 8);
            }
            CPCOMMIT();
            CPWAIT1();
        } else {
            CPWAIT0();
        }
        __syncthreads();
        const uint32_t so = (uint32_t)(ch & 1) * G_STAGE;
#pragma unroll
        for (int ks = 0; ks < 2; ks++) {
            uint32_t ah[4][4], bh[4][2];
            const uint32_t aoff = (uint32_t)((lane & 15) * 80 +
                                  (ks * 16 + (lane >> 4) * 8) * 2) + so;
#pragma unroll
            for (int mb = 0; mb < 4; mb++)
                ldsm4(ah[mb], SAH + (uint32_t)(wm + mb * 16) * 80u + aoff);
            const uint32_t boff = (uint32_t)((lane & 7) * 80 +
                                  (ks * 16 + ((lane >> 3) & 1) * 8) * 2) + so;
#pragma unroll
            for (int nb = 0; nb < 4; nb++)
                ldsm2(bh[nb], SBH + (uint32_t)(wn + nb * 8) * 80u + boff);
#pragma unroll
            for (int mb = 0; mb < 4; mb++)
#pragma unroll
                for (int nb = 0; nb < 4; nb++)
                    mma16816(acc[mb][nb], ah[mb], bh[nb]);
        }
        __syncthreads();
    }

    // epilogue
    const int lr = lane >> 2, lc = (lane & 3) * 2;
    const float sc = (mode == 0) ? 0.125f : 1.0f;
#pragma unroll
    for (int mb = 0; mb < 4; mb++) {
#pragma unroll
        for (int nb = 0; nb < 4; nb++) {
            const int col = n0 + wn + nb * 8 + lc;
            const float b0 = bias[col], b1 = bias[col + 1];
#pragma unroll
            for (int half_ = 0; half_ < 2; half_++) {
                const int row = m0 + wm + mb * 16 + lr + 8 * half_;
                const float v0 = (acc[mb][nb][2 * half_] + b0) * sc;
                const float v1 = (acc[mb][nb][2 * half_ + 1] + b1) * sc;
                const int bb = row >> 11, ss = row & (S_LEN - 1);
                const int h = col >> 6, d = col & 63;
                if (mode == 0 || mode == 1) {   // Q,K: fp16 headlayout
                    const size_t base = (((size_t)(bb * NH + h) * S_LEN + ss) << 6) + d;
                    *(uint32_t*)(Oh + base) = pcvt2(v0, v1);
                } else if (mode == 2) {          // V: fp16 transposed
                    const size_t base = ((size_t)(bb * NH + h) * DK + d) * S_LEN + ss;
                    Oh[base] = __float2half_rn(v0);
                    Oh[base + S_LEN] = __float2half_rn(v1);
                } else {
                    *(float2*)(Of + (size_t)row * DM + col) = make_float2(v0, v1);
                }
            }
        }
    }
}

// ---------------------------------------------------------------------------
// mma.sync flash attention, pure fp16 operands, fp32 accumulators.
// No-max softmax (scores bounded, 1/8 folded in Q). CTA: 128 q-rows x (b,h),
// 256 thr (8 warps x 16 rows). KV chunks of 64, cp.async 2-stage.
// ---------------------------------------------------------------------------
#define AP 72                     // padded row stride (elements) = 144B: conflict-free
#define A_QBYTES (128 * AP * 2)   // 18432
#define A_STAGE  (64 * AP * 2)    // 9216
#define A_SMEM   (A_QBYTES + 4 * A_STAGE)   // 55296

__global__ __launch_bounds__(256, 2) void attn_mma_kernel(
    const __half* __restrict__ Qh, const __half* __restrict__ Kh,
    const __half* __restrict__ Vth, __half* __restrict__ AO)
{
    extern __shared__ char smc[];
    const uint32_t smb = smem_u32(smc);
    const int tid = threadIdx.x, lane = tid & 31, wid = tid >> 5;
    const int bh = blockIdx.y;
    const int q0 = blockIdx.x * 128;
    const uint32_t SQH = smb;
    const uint32_t SKH = smb + A_QBYTES, SVH = SKH + 2 * A_STAGE;

    const size_t qbase = ((size_t)bh * S_LEN + q0) * DK;
    const size_t kbase = (size_t)bh * S_LEN * DK;
    const size_t vbase = (size_t)bh * DK * S_LEN;

    // prologue: Q (1024 segs) + K,V chunk 0 (512 segs each)
    {
#pragma unroll
        for (int p = 0; p < 4; p++) {
            const int idx = tid + p * 256, r = idx >> 3, c = idx & 7;
            CP16(SQH + (uint32_t)r * 144u + (uint32_t)c * 16u,
                 Qh + qbase + (size_t)r * DK + c * 8);
        }
#pragma unroll
        for (int p = 0; p < 2; p++) {
            const int idx = tid + p * 256, r = idx >> 3, c = idx & 7;
            const uint32_t d = (uint32_t)r * 144u + (uint32_t)c * 16u;
            CP16(SKH + d, Kh + kbase + (size_t)r * DK + c * 8);
            CP16(SVH + d, Vth + vbase + (size_t)r * S_LEN + c * 8);
        }
        CPCOMMIT();
    }

    const int r0 = wid * 16;
    float oacc[8][4];
    float lsum[2] = {0.f, 0.f};
#pragma unroll
    for (int db = 0; db < 8; db++)
#pragma unroll
        for (int e = 0; e < 4; e++) oacc[db][e] = 0.f;

    for (int i = 0; i < 32; i++) {
        if (i + 1 < 32) {
            const int t0 = (i + 1) * 64;
            const uint32_t so = (uint32_t)((i + 1) & 1) * A_STAGE;
#pragma unroll
            for (int p = 0; p < 2; p++) {
                const int idx = tid + p * 256, r = idx >> 3, c = idx & 7;
                const uint32_t d = (uint32_t)r * 144u + (uint32_t)c * 16u + so;
                CP16(SKH + d, Kh + kbase + (size_t)(t0 + r) * DK + c * 8);
                CP16(SVH + d, Vth + vbase + (size_t)r * S_LEN + t0 + c * 8);
            }
            CPCOMMIT();
            CPWAIT1();
        } else {
            CPWAIT0();
        }
        __syncthreads();
        const uint32_t so = (uint32_t)(i & 1) * A_STAGE;

        // ---- MMA1: S[16 x 64] = Q @ K^T ----
        float sacc[8][4];
#pragma unroll
        for (int nb = 0; nb < 8; nb++)
#pragma unroll
            for (int e = 0; e < 4; e++) sacc[nb][e] = 0.f;
#pragma unroll
        for (int ks = 0; ks < 4; ks++) {
            uint32_t qf[4];
            ldsm4(qf, SQH + (uint32_t)((r0 + (lane & 15)) * 144 +
                                       (ks * 16 + (lane >> 4) * 8) * 2));
            const uint32_t bo = (uint32_t)((lane & 7) * 144 +
                                 (ks * 16 + ((lane >> 3) & 1) * 8) * 2) + so;
#pragma unroll
            for (int nb = 0; nb < 8; nb++) {
                uint32_t kb[2];
                ldsm2(kb, SKH + (uint32_t)(nb * 8) * 144u + bo);
                mma16816(sacc[nb], qf, kb);
            }
        }

        // ---- exp + row-sum partials (no max subtraction) ----
#pragma unroll
        for (int nb = 0; nb < 8; nb++)
#pragma unroll
            for (int e = 0; e < 4; e++) {
                const float p = __expf(sacc[nb][e]);
                lsum[e >> 1] += p;
                sacc[nb][e] = p;
            }

        // ---- MMA2: O[16 x 64] += P @ Vh; P from registers (fp16) ----
#pragma unroll
        for (int ts = 0; ts < 4; ts++) {
            uint32_t ph[4];
            ph[0] = pcvt2(sacc[2 * ts][0],     sacc[2 * ts][1]);
            ph[1] = pcvt2(sacc[2 * ts][2],     sacc[2 * ts][3]);
            ph[2] = pcvt2(sacc[2 * ts + 1][0], sacc[2 * ts + 1][1]);
            ph[3] = pcvt2(sacc[2 * ts + 1][2], sacc[2 * ts + 1][3]);
            const uint32_t vo = (uint32_t)((lane & 7) * 144 +
                                 (ts * 16 + ((lane >> 3) & 1) * 8) * 2) + so;
#pragma unroll
            for (int db = 0; db < 8; db++) {
                uint32_t vb[2];
                ldsm2(vb, SVH + (uint32_t)(db * 8) * 144u + vo);
                mma16816(oacc[db], ph, vb);
            }
        }
        __syncthreads();
    }

    // ---- row-sum reduction across the 4 lanes owning each row ----
#pragma unroll
    for (int e = 0; e < 2; e++) {
        lsum[e] += __shfl_xor_sync(0xffffffffu, lsum[e], 1);
        lsum[e] += __shfl_xor_sync(0xffffffffu, lsum[e], 2);
    }
    const float inv0 = 1.f / lsum[0], inv1 = 1.f / lsum[1];

    // ---- epilogue: att fp16 [b][s][h*64+d] ----
    const int bb = bh >> 4, hh = bh & 15;
    const int rowa = q0 + r0 + (lane >> 2);
#pragma unroll
    for (int db = 0; db < 8; db++) {
        const int col = hh * 64 + db * 8 + (lane & 3) * 2;
        const size_t ba = ((size_t)bb * S_LEN + rowa) * DM + col;
        const size_t bb2 = ba + (size_t)8 * DM;
        *(uint32_t*)(AO + ba)  = pcvt2(oacc[db][0] * inv0, oacc[db][1] * inv0);
        *(uint32_t*)(AO + bb2) = pcvt2(oacc[db][2] * inv1, oacc[db][3] * inv1);
    }
}

// ---------------------------------------------------------------------------
extern "C" void kernel_launch(void* const* d_in, const int* in_sizes, int n_in,
                              void* d_out, int out_size)
{
    const float* q  = (const float*)d_in[0];
    const float* k  = (const float*)d_in[1];
    const float* v  = (const float*)d_in[2];
    const float* Wq = (const float*)d_in[3];
    const float* bq = (const float*)d_in[4];
    const float* Wk = (const float*)d_in[5];
    const float* bk = (const float*)d_in[6];
    const float* Wv = (const float*)d_in[7];
    const float* bv = (const float*)d_in[8];
    const float* Wo = (const float*)d_in[9];
    const float* bo = (const float*)d_in[10];
    float* out = (float*)d_out;

    __half *inq, *ink, *inv, *qh, *kh, *vt, *at, *wq, *wk, *wv, *wo;
    cudaGetSymbolAddress((void**)&inq, g_inq);
    cudaGetSymbolAddress((void**)&ink, g_ink);
    cudaGetSymbolAddress((void**)&inv, g_inv);
    cudaGetSymbolAddress((void**)&qh,  g_q);
    cudaGetSymbolAddress((void**)&kh,  g_k);
    cudaGetSymbolAddress((void**)&vt,  g_vt);
    cudaGetSymbolAddress((void**)&at,  g_at);
    cudaGetSymbolAddress((void**)&wq,  g_wq);
    cudaGetSymbolAddress((void**)&wk,  g_wk);
    cudaGetSymbolAddress((void**)&wv,  g_wv);
    cudaGetSymbolAddress((void**)&wo,  g_wo);

    cudaFuncSetAttribute(gemm_mma_kernel, cudaFuncAttributeMaxDynamicSharedMemorySize, G_SMEM);
    cudaFuncSetAttribute(attn_mma_kernel, cudaFuncAttributeMaxDynamicSharedMemorySize, A_SMEM);

    // input converts (fp32 -> fp16)
    const int nblk = (MROWS * DM / 4) / 256;   // 4096
    cvt_kernel<<<nblk, 256>>>(q, inq);
    cvt_kernel<<<nblk, 256>>>(k, ink);
    cvt_kernel<<<nblk, 256>>>(v, inv);

    // weight transpose + convert
    dim3 wg(32, 32);
    wsplit_kernel<<<wg, 256>>>(Wq, wq);
    wsplit_kernel<<<wg, 256>>>(Wk, wk);
    wsplit_kernel<<<wg, 256>>>(Wv, wv);
    wsplit_kernel<<<wg, 256>>>(Wo, wo);

    // projections
    dim3 gg(DM / 128, MROWS / 128);
    gemm_mma_kernel<<<gg, 256, G_SMEM>>>(inq, wq, bq, qh, nullptr, 0);
    gemm_mma_kernel<<<gg, 256, G_SMEM>>>(ink, wk, bk, kh, nullptr, 1);
    gemm_mma_kernel<<<gg, 256, G_SMEM>>>(inv, wv, bv, vt, nullptr, 2);

    // attention
    dim3 ga(S_LEN / 128, NB * NH);
    attn_mma_kernel<<<ga, 256, A_SMEM>>>(qh, kh, vt, at);

    // output projection
    gemm_mma_kernel<<<gg, 256, G_SMEM>>>(at, wo, bo, nullptr, out, 3);
}

// round 10
// speedup vs baseline: 1.7139x; 1.0510x over previous
#include <cuda_runtime.h>
#include <cuda_fp16.h>
#include <cstdint>

#define S_LEN 2048
#define NB 2
#define NH 16
#define DK 64
#define DM 1024
#define MROWS (NB * S_LEN)   // 4096
#define HEADELEMS ((size_t)NB * NH * S_LEN * DK)

// ---------------- scratch (__device__ globals; no allocs allowed) ----------
__device__ __half g_q[HEADELEMS];                        // [b,h][t][d], 1/8 folded
__device__ __half g_k[HEADELEMS];                        // [b,h][t][d]
__device__ __half g_vt[HEADELEMS];                       // [b,h][d][t]
__device__ __half g_at[(size_t)MROWS * DM];              // attention out [b][s][h*64+d]
__device__ __half g_wq[DM * DM], g_wk[DM * DM], g_wv[DM * DM], g_wo[DM * DM];

// ---------------- PTX helpers (all valid on non-'a' compute_103) -----------
__device__ __forceinline__ uint32_t smem_u32(const void* p) {
    uint32_t a;
    asm("{ .reg .u64 t; cvta.to.shared.u64 t, %1; cvt.u32.u64 %0, t; }" : "=r"(a) : "l"(p));
    return a;
}
#define CP16(dst, src) asm volatile("cp.async.ca.shared.global [%0], [%1], 16;" :: "r"(dst), "l"(src))
#define CPCOMMIT()     asm volatile("cp.async.commit_group;" ::: "memory")
#define CPWAIT1()      asm volatile("cp.async.wait_group 1;" ::: "memory")
#define CPWAIT0()      asm volatile("cp.async.wait_group 0;" ::: "memory")

__device__ __forceinline__ void ldsm4(uint32_t* r, uint32_t a) {
    asm volatile("ldmatrix.sync.aligned.m8n8.x4.shared.b16 {%0,%1,%2,%3}, [%4];"
                 : "=r"(r[0]), "=r"(r[1]), "=r"(r[2]), "=r"(r[3]) : "r"(a));
}
__device__ __forceinline__ void ldsm2(uint32_t* r, uint32_t a) {
    asm volatile("ldmatrix.sync.aligned.m8n8.x2.shared.b16 {%0,%1}, [%2];"
                 : "=r"(r[0]), "=r"(r[1]) : "r"(a));
}
__device__ __forceinline__ void mma16816(float* d, const uint32_t* a, const uint32_t* b) {
    asm volatile("mma.sync.aligned.m16n8k16.row.col.f32.f16.f16.f32 "
                 "{%0,%1,%2,%3},{%4,%5,%6,%7},{%8,%9},{%0,%1,%2,%3};"
                 : "+f"(d[0]), "+f"(d[1]), "+f"(d[2]), "+f"(d[3])
                 : "r"(a[0]), "r"(a[1]), "r"(a[2]), "r"(a[3]), "r"(b[0]), "r"(b[1]));
}

__device__ __forceinline__ uint32_t pack2(uint16_t a, uint16_t b) {
    return (uint32_t)a | ((uint32_t)b << 16);
}
__device__ __forceinline__ uint32_t pcvt2(float x, float y) {
    return pack2(__half_as_ushort(__float2half_rn(x)),
                 __half_as_ushort(__float2half_rn(y)));
}

// ---------------------------------------------------------------------------
// Fused weight transpose + convert (z selects which W):  T[n][k] = fp16(W[k][n])
// ---------------------------------------------------------------------------
__global__ __launch_bounds__(256) void wsplit_kernel(
    const float* __restrict__ W0, const float* __restrict__ W1,
    const float* __restrict__ W2, const float* __restrict__ W3,
    __half* __restrict__ T0, __half* __restrict__ T1,
    __half* __restrict__ T2, __half* __restrict__ T3)
{
    const int z = blockIdx.z;
    const float* W = (z == 0) ? W0 : (z == 1) ? W1 : (z == 2) ? W2 : W3;
    __half* Th     = (z == 0) ? T0 : (z == 1) ? T1 : (z == 2) ? T2 : T3;

    __shared__ float ts[32][33];
    const int tid = threadIdx.x;
    const int tx = tid & 31, ty = tid >> 5;                 // ty: 0..7
    const int k0 = blockIdx.x * 32, n0 = blockIdx.y * 32;
#pragma unroll
    for (int p = 0; p < 4; p++)
        ts[ty + 8 * p][tx] = W[(size_t)(k0 + ty + 8 * p) * DM + n0 + tx];
    __syncthreads();
#pragma unroll
    for (int p = 0; p < 4; p++) {
        const int r = ty + 8 * p;                            // local n
        Th[(size_t)(n0 + r) * DM + k0 + tx] = __float2half_rn(ts[tx][r]);
    }
}

// ---------------------------------------------------------------------------
// Fused QKV GEMM (z selects q/k/v): C = A_fp32 @ W^T + bias.
// A: fp32, converted fp16 during staging (register double buffer).
// B: fp16 pre-transposed weights via cp.async 2-stage.
// z=0: -> fp16 headlayout, scale 1/8 (Q);  z=1: headlayout (K);
// z=2: -> fp16 transposed [b,h][d][t] via smem-bounce coalesced stores (V).
// ---------------------------------------------------------------------------
#define GP 40                   // padded row stride (elements); 80B rows
#define G_STAGE (128 * GP * 2)  // 10240 bytes
#define G_SMEM  (4 * G_STAGE)   // 40960 (also >= 128*136*2 for V transpose bounce)
#define TPAD 136                // V-bounce row stride (half elems)

__global__ __launch_bounds__(256, 2) void gemm_qkv_kernel(
    const float* __restrict__ A0, const float* __restrict__ A1,
    const float* __restrict__ A2,
    const __half* __restrict__ B0, const __half* __restrict__ B1,
    const __half* __restrict__ B2,
    const float* __restrict__ bias0, const float* __restrict__ bias1,
    const float* __restrict__ bias2,
    __half* __restrict__ O0, __half* __restrict__ O1, __half* __restrict__ O2)
{
    extern __shared__ char smc[];
    const uint32_t smb = smem_u32(smc);
    const int z = blockIdx.z;
    const float*  A    = (z == 0) ? A0 : (z == 1) ? A1 : A2;
    const __half* Bh   = (z == 0) ? B0 : (z == 1) ? B1 : B2;
    const float*  bias = (z == 0) ? bias0 : (z == 1) ? bias1 : bias2;
    __half* Oh         = (z == 0) ? O0 : (z == 1) ? O1 : O2;

    const int tid = threadIdx.x, lane = tid & 31, wid = tid >> 5;
    const int m0 = blockIdx.y * 128, n0 = blockIdx.x * 128;
    const int wm = (wid >> 2) * 64, wn = (wid & 3) * 32;
    const uint32_t SAH = smb, SBH = smb + 2 * G_STAGE;

    // A loader mapping: 2 segs/thread, seg = (r = idx>>2) row, (c = idx&3) x16B col
    const int r0a = tid >> 2, c0a = tid & 3;          // seg p adds 64 to r

    // prologue: A chunk 0 -> regs; B chunk 0 -> cp.async
    float4 areg[2][2];
#pragma unroll
    for (int p = 0; p < 2; p++) {
        const float* src = A + (size_t)(m0 + r0a + p * 64) * DM + c0a * 8;
        areg[p][0] = ((const float4*)src)[0];
        areg[p][1] = ((const float4*)src)[1];
    }
#pragma unroll
    for (int p = 0; p < 2; p++) {
        const int idx = tid + p * 256, r = idx >> 2, c = idx & 3;
        CP16(SBH + (uint32_t)r * 80u + (uint32_t)c * 16u,
             Bh + (size_t)(n0 + r) * DM + c * 8);
    }
    CPCOMMIT();

    float acc[4][4][4];
#pragma unroll
    for (int a = 0; a < 4; a++)
#pragma unroll
        for (int b = 0; b < 4; b++)
#pragma unroll
            for (int c = 0; c < 4; c++) acc[a][b][c] = 0.f;

    for (int ch = 0; ch < 32; ch++) {
        const uint32_t so = (uint32_t)(ch & 1) * G_STAGE;
        if (ch + 1 < 32) {
            const int k0 = (ch + 1) * 32;
            const uint32_t sn = (uint32_t)((ch + 1) & 1) * G_STAGE;
#pragma unroll
            for (int p = 0; p < 2; p++) {
                const int idx = tid + p * 256, r = idx >> 2, c = idx & 3;
                CP16(SBH + (uint32_t)r * 80u + (uint32_t)c * 16u + sn,
                     Bh + (size_t)(n0 + r) * DM + k0 + c * 8);
            }
            CPCOMMIT();
        }
        // stage A chunk ch (convert fp32->fp16)
#pragma unroll
        for (int p = 0; p < 2; p++) {
            uint4 v;
            v.x = pcvt2(areg[p][0].x, areg[p][0].y);
            v.y = pcvt2(areg[p][0].z, areg[p][0].w);
            v.z = pcvt2(areg[p][1].x, areg[p][1].y);
            v.w = pcvt2(areg[p][1].z, areg[p][1].w);
            *(uint4*)(smc + (SAH - smb) + (uint32_t)(r0a + p * 64) * 80u +
                      (uint32_t)c0a * 16u + so) = v;
        }
        // load A chunk ch+1 into regs
        if (ch + 1 < 32) {
            const int k0 = (ch + 1) * 32;
#pragma unroll
            for (int p = 0; p < 2; p++) {
                const float* src = A + (size_t)(m0 + r0a + p * 64) * DM + k0 + c0a * 8;
                areg[p][0] = ((const float4*)src)[0];
                areg[p][1] = ((const float4*)src)[1];
            }
            CPWAIT1();
        } else {
            CPWAIT0();
        }
        __syncthreads();
#pragma unroll
        for (int ks = 0; ks < 2; ks++) {
            uint32_t ah[4][4], bh[4][2];
            const uint32_t aoff = (uint32_t)((lane & 15) * 80 +
                                  (ks * 16 + (lane >> 4) * 8) * 2) + so;
#pragma unroll
            for (int mb = 0; mb < 4; mb++)
                ldsm4(ah[mb], SAH + (uint32_t)(wm + mb * 16) * 80u + aoff);
            const uint32_t boff = (uint32_t)((lane & 7) * 80 +
                                  (ks * 16 + ((lane >> 3) & 1) * 8) * 2) + so;
#pragma unroll
            for (int nb = 0; nb < 4; nb++)
                ldsm2(bh[nb], SBH + (uint32_t)(wn + nb * 8) * 80u + boff);
#pragma unroll
            for (int mb = 0; mb < 4; mb++)
#pragma unroll
                for (int nb = 0; nb < 4; nb++)
                    mma16816(acc[mb][nb], ah[mb], bh[nb]);
        }
        __syncthreads();
    }

    // epilogue
    const int lr = lane >> 2, lc = (lane & 3) * 2;
    if (z != 2) {
        const float sc = (z == 0) ? 0.125f : 1.0f;
#pragma unroll
        for (int mb = 0; mb < 4; mb++) {
#pragma unroll
            for (int nb = 0; nb < 4; nb++) {
                const int col = n0 + wn + nb * 8 + lc;
                const float b0 = bias[col], b1 = bias[col + 1];
#pragma unroll
                for (int half_ = 0; half_ < 2; half_++) {
                    const int row = m0 + wm + mb * 16 + lr + 8 * half_;
                    const float v0 = (acc[mb][nb][2 * half_] + b0) * sc;
                    const float v1 = (acc[mb][nb][2 * half_ + 1] + b1) * sc;
                    const int bb = row >> 11, ss = row & (S_LEN - 1);
                    const int h = col >> 6, d = col & 63;
                    const size_t base = (((size_t)(bb * NH + h) * S_LEN + ss) << 6) + d;
                    *(uint32_t*)(Oh + base) = pcvt2(v0, v1);
                }
            }
        }
    } else {
        // V: transpose-bounce through smem, then coalesced 16B stores
        __half* tsm = (__half*)smc;   // [128 cols][TPAD] (col = local n = d)
#pragma unroll
        for (int mb = 0; mb < 4; mb++) {
#pragma unroll
            for (int nb = 0; nb < 4; nb++) {
                const int col = wn + nb * 8 + lc;
                const float b0 = bias[n0 + col], b1 = bias[n0 + col + 1];
#pragma unroll
                for (int half_ = 0; half_ < 2; half_++) {
                    const int row = wm + mb * 16 + lr + 8 * half_;
                    tsm[(size_t)col * TPAD + row] =
                        __float2half_rn(acc[mb][nb][2 * half_] + b0);
                    tsm[(size_t)(col + 1) * TPAD + row] =
                        __float2half_rn(acc[mb][nb][2 * half_ + 1] + b1);
                }
            }
        }
        __syncthreads();
        // read out: thread pair covers one d; 64 t each; 16B chunks
        const int dl = tid >> 1;                    // local col (d) 0..127
        const int tof = (tid & 1) * 64;             // t half
        const int row = m0;                         // t base (within one batch)
        const int bb = row >> 11, ss0 = (row & (S_LEN - 1)) + tof;
        const int n = n0 + dl, h = n >> 6, d = n & 63;
        __half* dst = Oh + ((size_t)(bb * NH + h) * DK + d) * S_LEN + ss0;
        const __half* srcr = tsm + (size_t)dl * TPAD + tof;
#pragma unroll
        for (int j = 0; j < 8; j++)
            ((uint4*)dst)[j] = ((const uint4*)srcr)[j];
    }
}

// ---------------------------------------------------------------------------
// Output projection GEMM: out_fp32 = att_fp16 @ Wo^T + bo (cp.async both sides)
// ---------------------------------------------------------------------------
__global__ __launch_bounds__(256, 2) void gemm_o_kernel(
    const __half* __restrict__ Ah, const __half* __restrict__ Bh,
    const float* __restrict__ bias, float* __restrict__ Of)
{
    extern __shared__ char smc[];
    const uint32_t smb = smem_u32(smc);
    const int tid = threadIdx.x, lane = tid & 31, wid = tid >> 5;
    const int m0 = blockIdx.y * 128, n0 = blockIdx.x * 128;
    const int wm = (wid >> 2) * 64, wn = (wid & 3) * 32;
    const uint32_t SAH = smb, SBH = smb + 2 * G_STAGE;

#pragma unroll
    for (int p = 0; p < 2; p++) {
        const int idx = tid + p * 256, r = idx >> 2, c = idx & 3;
        const uint32_t d = (uint32_t)r * 80u + (uint32_t)c * 16u;
        CP16(SAH + d, Ah + (size_t)(m0 + r) * DM + c * 8);
        CP16(SBH + d, Bh + (size_t)(n0 + r) * DM + c * 8);
    }
    CPCOMMIT();

    float acc[4][4][4];
#pragma unroll
    for (int a = 0; a < 4; a++)
#pragma unroll
        for (int b = 0; b < 4; b++)
#pragma unroll
            for (int c = 0; c < 4; c++) acc[a][b][c] = 0.f;

    for (int ch = 0; ch < 32; ch++) {
        if (ch + 1 < 32) {
            const int k0 = (ch + 1) * 32;
            const uint32_t so = (uint32_t)((ch + 1) & 1) * G_STAGE;
#pragma unroll
            for (int p = 0; p < 2; p++) {
                const int idx = tid + p * 256, r = idx >> 2, c = idx & 3;
                const uint32_t d = (uint32_t)r * 80u + (uint32_t)c * 16u + so;
                CP16(SAH + d, Ah + (size_t)(m0 + r) * DM + k0 + c * 8);
                CP16(SBH + d, Bh + (size_t)(n0 + r) * DM + k0 + c * 8);
            }
            CPCOMMIT();
            CPWAIT1();
        } else {
            CPWAIT0();
        }
        __syncthreads();
        const uint32_t so = (uint32_t)(ch & 1) * G_STAGE;
#pragma unroll
        for (int ks = 0; ks < 2; ks++) {
            uint32_t ah[4][4], bh[4][2];
            const uint32_t aoff = (uint32_t)((lane & 15) * 80 +
                                  (ks * 16 + (lane >> 4) * 8) * 2) + so;
#pragma unroll
            for (int mb = 0; mb < 4; mb++)
                ldsm4(ah[mb], SAH + (uint32_t)(wm + mb * 16) * 80u + aoff);
            const uint32_t boff = (uint32_t)((lane & 7) * 80 +
                                  (ks * 16 + ((lane >> 3) & 1) * 8) * 2) + so;
#pragma unroll
            for (int nb = 0; nb < 4; nb++)
                ldsm2(bh[nb], SBH + (uint32_t)(wn + nb * 8) * 80u + boff);
#pragma unroll
            for (int mb = 0; mb < 4; mb++)
#pragma unroll
                for (int nb = 0; nb < 4; nb++)
                    mma16816(acc[mb][nb], ah[mb], bh[nb]);
        }
        __syncthreads();
    }

    const int lr = lane >> 2, lc = (lane & 3) * 2;
#pragma unroll
    for (int mb = 0; mb < 4; mb++) {
#pragma unroll
        for (int nb = 0; nb < 4; nb++) {
            const int col = n0 + wn + nb * 8 + lc;
            const float b0 = bias[col], b1 = bias[col + 1];
#pragma unroll
            for (int half_ = 0; half_ < 2; half_++) {
                const int row = m0 + wm + mb * 16 + lr + 8 * half_;
                *(float2*)(Of + (size_t)row * DM + col) =
                    make_float2(acc[mb][nb][2 * half_] + b0,
                                acc[mb][nb][2 * half_ + 1] + b1);
            }
        }
    }
}

// ---------------------------------------------------------------------------
// mma.sync flash attention, pure fp16 operands, fp32 accumulators.
// (unchanged from R9)
// ---------------------------------------------------------------------------
#define AP 72
#define A_QBYTES (128 * AP * 2)   // 18432
#define A_STAGE  (64 * AP * 2)    // 9216
#define A_SMEM   (A_QBYTES + 4 * A_STAGE)   // 55296

__global__ __launch_bounds__(256, 2) void attn_mma_kernel(
    const __half* __restrict__ Qh, const __half* __restrict__ Kh,
    const __half* __restrict__ Vth, __half* __restrict__ AO)
{
    extern __shared__ char smc[];
    const uint32_t smb = smem_u32(smc);
    const int tid = threadIdx.x, lane = tid & 31, wid = tid >> 5;
    const int bh = blockIdx.y;
    const int q0 = blockIdx.x * 128;
    const uint32_t SQH = smb;
    const uint32_t SKH = smb + A_QBYTES, SVH = SKH + 2 * A_STAGE;

    const size_t qbase = ((size_t)bh * S_LEN + q0) * DK;
    const size_t kbase = (size_t)bh * S_LEN * DK;
    const size_t vbase = (size_t)bh * DK * S_LEN;

    {
#pragma unroll
        for (int p = 0; p < 4; p++) {
            const int idx = tid + p * 256, r = idx >> 3, c = idx & 7;
            CP16(SQH + (uint32_t)r * 144u + (uint32_t)c * 16u,
                 Qh + qbase + (size_t)r * DK + c * 8);
        }
#pragma unroll
        for (int p = 0; p < 2; p++) {
            const int idx = tid + p * 256, r = idx >> 3, c = idx & 7;
            const uint32_t d = (uint32_t)r * 144u + (uint32_t)c * 16u;
            CP16(SKH + d, Kh + kbase + (size_t)r * DK + c * 8);
            CP16(SVH + d, Vth + vbase + (size_t)r * S_LEN + c * 8);
        }
        CPCOMMIT();
    }

    const int r0 = wid * 16;
    float oacc[8][4];
    float lsum[2] = {0.f, 0.f};
#pragma unroll
    for (int db = 0; db < 8; db++)
#pragma unroll
        for (int e = 0; e < 4; e++) oacc[db][e] = 0.f;

    for (int i = 0; i < 32; i++) {
        if (i + 1 < 32) {
            const int t0 = (i + 1) * 64;
            const uint32_t so = (uint32_t)((i + 1) & 1) * A_STAGE;
#pragma unroll
            for (int p = 0; p < 2; p++) {
                const int idx = tid + p * 256, r = idx >> 3, c = idx & 7;
                const uint32_t d = (uint32_t)r * 144u + (uint32_t)c * 16u + so;
                CP16(SKH + d, Kh + kbase + (size_t)(t0 + r) * DK + c * 8);
                CP16(SVH + d, Vth + vbase + (size_t)r * S_LEN + t0 + c * 8);
            }
            CPCOMMIT();
            CPWAIT1();
        } else {
            CPWAIT0();
        }
        __syncthreads();
        const uint32_t so = (uint32_t)(i & 1) * A_STAGE;

        float sacc[8][4];
#pragma unroll
        for (int nb = 0; nb < 8; nb++)
#pragma unroll
            for (int e = 0; e < 4; e++) sacc[nb][e] = 0.f;
#pragma unroll
        for (int ks = 0; ks < 4; ks++) {
            uint32_t qf[4];
            ldsm4(qf, SQH + (uint32_t)((r0 + (lane & 15)) * 144 +
                                       (ks * 16 + (lane >> 4) * 8) * 2));
            const uint32_t bo = (uint32_t)((lane & 7) * 144 +
                                 (ks * 16 + ((lane >> 3) & 1) * 8) * 2) + so;
#pragma unroll
            for (int nb = 0; nb < 8; nb++) {
                uint32_t kb[2];
                ldsm2(kb, SKH + (uint32_t)(nb * 8) * 144u + bo);
                mma16816(sacc[nb], qf, kb);
            }
        }

#pragma unroll
        for (int nb = 0; nb < 8; nb++)
#pragma unroll
            for (int e = 0; e < 4; e++) {
                const float p = __expf(sacc[nb][e]);
                lsum[e >> 1] += p;
                sacc[nb][e] = p;
            }

#pragma unroll
        for (int ts = 0; ts < 4; ts++) {
            uint32_t ph[4];
            ph[0] = pcvt2(sacc[2 * ts][0],     sacc[2 * ts][1]);
            ph[1] = pcvt2(sacc[2 * ts][2],     sacc[2 * ts][3]);
            ph[2] = pcvt2(sacc[2 * ts + 1][0], sacc[2 * ts + 1][1]);
            ph[3] = pcvt2(sacc[2 * ts + 1][2], sacc[2 * ts + 1][3]);
            const uint32_t vo = (uint32_t)((lane & 7) * 144 +
                                 (ts * 16 + ((lane >> 3) & 1) * 8) * 2) + so;
#pragma unroll
            for (int db = 0; db < 8; db++) {
                uint32_t vb[2];
                ldsm2(vb, SVH + (uint32_t)(db * 8) * 144u + vo);
                mma16816(oacc[db], ph, vb);
            }
        }
        __syncthreads();
    }

#pragma unroll
    for (int e = 0; e < 2; e++) {
        lsum[e] += __shfl_xor_sync(0xffffffffu, lsum[e], 1);
        lsum[e] += __shfl_xor_sync(0xffffffffu, lsum[e], 2);
    }
    const float inv0 = 1.f / lsum[0], inv1 = 1.f / lsum[1];

    const int bb = bh >> 4, hh = bh & 15;
    const int rowa = q0 + r0 + (lane >> 2);
#pragma unroll
    for (int db = 0; db < 8; db++) {
        const int col = hh * 64 + db * 8 + (lane & 3) * 2;
        const size_t ba = ((size_t)bb * S_LEN + rowa) * DM + col;
        const size_t bb2 = ba + (size_t)8 * DM;
        *(uint32_t*)(AO + ba)  = pcvt2(oacc[db][0] * inv0, oacc[db][1] * inv0);
        *(uint32_t*)(AO + bb2) = pcvt2(oacc[db][2] * inv1, oacc[db][3] * inv1);
    }
}

// ---------------------------------------------------------------------------
extern "C" void kernel_launch(void* const* d_in, const int* in_sizes, int n_in,
                              void* d_out, int out_size)
{
    const float* q  = (const float*)d_in[0];
    const float* k  = (const float*)d_in[1];
    const float* v  = (const float*)d_in[2];
    const float* Wq = (const float*)d_in[3];
    const float* bq = (const float*)d_in[4];
    const float* Wk = (const float*)d_in[5];
    const float* bk = (const float*)d_in[6];
    const float* Wv = (const float*)d_in[7];
    const float* bv = (const float*)d_in[8];
    const float* Wo = (const float*)d_in[9];
    const float* bo = (const float*)d_in[10];
    float* out = (float*)d_out;

    __half *qh, *kh, *vt, *at, *wq, *wk, *wv, *wo;
    cudaGetSymbolAddress((void**)&qh, g_q);
    cudaGetSymbolAddress((void**)&kh, g_k);
    cudaGetSymbolAddress((void**)&vt, g_vt);
    cudaGetSymbolAddress((void**)&at, g_at);
    cudaGetSymbolAddress((void**)&wq, g_wq);
    cudaGetSymbolAddress((void**)&wk, g_wk);
    cudaGetSymbolAddress((void**)&wv, g_wv);
    cudaGetSymbolAddress((void**)&wo, g_wo);

    cudaFuncSetAttribute(gemm_qkv_kernel, cudaFuncAttributeMaxDynamicSharedMemorySize, G_SMEM);
    cudaFuncSetAttribute(gemm_o_kernel, cudaFuncAttributeMaxDynamicSharedMemorySize, G_SMEM);
    cudaFuncSetAttribute(attn_mma_kernel, cudaFuncAttributeMaxDynamicSharedMemorySize, A_SMEM);

    // fused weight transpose + convert
    dim3 wg(32, 32, 4);
    wsplit_kernel<<<wg, 256>>>(Wq, Wk, Wv, Wo, wq, wk, wv, wo);

    // fused QKV projections (fp32 A converted in-kernel)
    dim3 gqkv(DM / 128, MROWS / 128, 3);
    gemm_qkv_kernel<<<gqkv, 256, G_SMEM>>>(q, k, v, wq, wk, wv, bq, bk, bv,
                                           qh, kh, vt);

    // attention
    dim3 ga(S_LEN / 128, NB * NH);
    attn_mma_kernel<<<ga, 256, A_SMEM>>>(qh, kh, vt, at);

    // output projection
    dim3 gg(DM / 128, MROWS / 128);
    gemm_o_kernel<<<gg, 256, G_SMEM>>>(at, wo, bo, out);
}

// round 12
// speedup vs baseline: 1.7712x; 1.0334x over previous
#include <cuda_runtime.h>
#include <cuda_fp16.h>
#include <cstdint>

#define S_LEN 2048
#define NB 2
#define NH 16
#define DK 64
#define DM 1024
#define MROWS (NB * S_LEN)   // 4096
#define HEADELEMS ((size_t)NB * NH * S_LEN * DK)

// ---------------- scratch (__device__ globals; no allocs allowed) ----------
__device__ __half g_q[HEADELEMS];                        // [b,h][t][d], 1/8 folded
__device__ __half g_k[HEADELEMS];                        // [b,h][t][d]
__device__ __half g_vt[HEADELEMS];                       // [b,h][d][t]
__device__ __half g_at[(size_t)MROWS * DM];              // attention out [b][s][h*64+d]
__device__ __half g_wq[DM * DM], g_wk[DM * DM], g_wv[DM * DM], g_wo[DM * DM];

// ---------------- PTX helpers ----------------------------------------------
__device__ __forceinline__ uint32_t smem_u32(const void* p) {
    uint32_t a;
    asm("{ .reg .u64 t; cvta.to.shared.u64 t, %1; cvt.u32.u64 %0, t; }" : "=r"(a) : "l"(p));
    return a;
}
#define CP16(dst, src) asm volatile("cp.async.ca.shared.global [%0], [%1], 16;" :: "r"(dst), "l"(src))
#define CPCOMMIT()     asm volatile("cp.async.commit_group;" ::: "memory")
#define CPWAIT0()      asm volatile("cp.async.wait_group 0;" ::: "memory")

__device__ __forceinline__ void ldsm4(uint32_t* r, uint32_t a) {
    asm volatile("ldmatrix.sync.aligned.m8n8.x4.shared.b16 {%0,%1,%2,%3}, [%4];"
                 : "=r"(r[0]), "=r"(r[1]), "=r"(r[2]), "=r"(r[3]) : "r"(a));
}
__device__ __forceinline__ void mma16816(float* d, const uint32_t* a, const uint32_t* b) {
    asm volatile("mma.sync.aligned.m16n8k16.row.col.f32.f16.f16.f32 "
                 "{%0,%1,%2,%3},{%4,%5,%6,%7},{%8,%9},{%0,%1,%2,%3};"
                 : "+f"(d[0]), "+f"(d[1]), "+f"(d[2]), "+f"(d[3])
                 : "r"(a[0]), "r"(a[1]), "r"(a[2]), "r"(a[3]), "r"(b[0]), "r"(b[1]));
}

__device__ __forceinline__ uint32_t pack2(uint16_t a, uint16_t b) {
    return (uint32_t)a | ((uint32_t)b << 16);
}
__device__ __forceinline__ uint32_t pcvt2(float x, float y) {
    return pack2(__half_as_ushort(__float2half_rn(x)),
                 __half_as_ushort(__float2half_rn(y)));
}

// ---------------------------------------------------------------------------
// Fused weight transpose + convert (z selects which W):  T[n][k] = fp16(W[k][n])
// ---------------------------------------------------------------------------
__global__ __launch_bounds__(256) void wsplit_kernel(
    const float* __restrict__ W0, const float* __restrict__ W1,
    const float* __restrict__ W2, const float* __restrict__ W3,
    __half* __restrict__ T0, __half* __restrict__ T1,
    __half* __restrict__ T2, __half* __restrict__ T3)
{
    const int z = blockIdx.z;
    const float* W = (z == 0) ? W0 : (z == 1) ? W1 : (z == 2) ? W2 : W3;
    __half* Th     = (z == 0) ? T0 : (z == 1) ? T1 : (z == 2) ? T2 : T3;

    __shared__ float ts[32][33];
    const int tid = threadIdx.x;
    const int tx = tid & 31, ty = tid >> 5;
    const int k0 = blockIdx.x * 32, n0 = blockIdx.y * 32;
#pragma unroll
    for (int p = 0; p < 4; p++)
        ts[ty + 8 * p][tx] = W[(size_t)(k0 + ty + 8 * p) * DM + n0 + tx];
    __syncthreads();
#pragma unroll
    for (int p = 0; p < 4; p++) {
        const int r = ty + 8 * p;
        Th[(size_t)(n0 + r) * DM + k0 + tx] = __float2half_rn(ts[tx][r]);
    }
}

// ---------------------------------------------------------------------------
// Fused QKV GEMM (z selects q/k/v): single-sync pipeline, B ldsm4-merged.
// ---------------------------------------------------------------------------
#define GP 40                   // 80B row stride: conflict-free ldsm phases
#define G_STAGE (128 * GP * 2)  // 10240 bytes
#define G_SMEM  (4 * G_STAGE)   // 40960 (also >= 128*136*2 V-bounce)
#define TPAD 136

__global__ __launch_bounds__(256, 2) void gemm_qkv_kernel(
    const float* __restrict__ A0, const float* __restrict__ A1,
    const float* __restrict__ A2,
    const __half* __restrict__ B0, const __half* __restrict__ B1,
    const __half* __restrict__ B2,
    const float* __restrict__ bias0, const float* __restrict__ bias1,
    const float* __restrict__ bias2,
    __half* __restrict__ O0, __half* __restrict__ O1, __half* __restrict__ O2)
{
    extern __shared__ char smc[];
    const uint32_t smb = smem_u32(smc);
    const int z = blockIdx.z;
    const float*  A    = (z == 0) ? A0 : (z == 1) ? A1 : A2;
    const __half* Bh   = (z == 0) ? B0 : (z == 1) ? B1 : B2;
    const float*  bias = (z == 0) ? bias0 : (z == 1) ? bias1 : bias2;
    __half* Oh         = (z == 0) ? O0 : (z == 1) ? O1 : O2;

    const int tid = threadIdx.x, lane = tid & 31, wid = tid >> 5;
    const int m0 = blockIdx.y * 128, n0 = blockIdx.x * 128;
    const int wm = (wid >> 2) * 64, wn = (wid & 3) * 32;
    const uint32_t SAH = smb, SBH = smb + 2 * G_STAGE;

    const int r0a = tid >> 2, c0a = tid & 3;

    // prologue: A chunk 0 -> regs; B chunk 0 -> cp.async
    float4 areg[2][2];
#pragma unroll
    for (int p = 0; p < 2; p++) {
        const float* src = A + (size_t)(m0 + r0a + p * 64) * DM + c0a * 8;
        areg[p][0] = ((const float4*)src)[0];
        areg[p][1] = ((const float4*)src)[1];
    }
#pragma unroll
    for (int p = 0; p < 2; p++) {
        const int idx = tid + p * 256, r = idx >> 2, c = idx & 3;
        CP16(SBH + (uint32_t)r * 80u + (uint32_t)c * 16u,
             Bh + (size_t)(n0 + r) * DM + c * 8);
    }
    CPCOMMIT();

    float acc[4][4][4];
#pragma unroll
    for (int a = 0; a < 4; a++)
#pragma unroll
        for (int b = 0; b < 4; b++)
#pragma unroll
            for (int c = 0; c < 4; c++) acc[a][b][c] = 0.f;

    for (int ch = 0; ch < 32; ch++) {
        const uint32_t so = (uint32_t)(ch & 1) * G_STAGE;
        // store A chunk ch (convert fp32->fp16); stage's last readers done
        // before the PREVIOUS iteration's sync.
#pragma unroll
        for (int p = 0; p < 2; p++) {
            uint4 v;
            v.x = pcvt2(areg[p][0].x, areg[p][0].y);
            v.y = pcvt2(areg[p][0].z, areg[p][0].w);
            v.z = pcvt2(areg[p][1].x, areg[p][1].y);
            v.w = pcvt2(areg[p][1].z, areg[p][1].w);
            *(uint4*)(smc + (uint32_t)(r0a + p * 64) * 80u +
                      (uint32_t)c0a * 16u + so) = v;
        }
        CPWAIT0();
        __syncthreads();
        if (ch + 1 < 32) {
            const int k0 = (ch + 1) * 32;
            const uint32_t sn = (uint32_t)((ch + 1) & 1) * G_STAGE;
#pragma unroll
            for (int p = 0; p < 2; p++) {
                const int idx = tid + p * 256, r = idx >> 2, c = idx & 3;
                CP16(SBH + (uint32_t)r * 80u + (uint32_t)c * 16u + sn,
                     Bh + (size_t)(n0 + r) * DM + k0 + c * 8);
            }
            CPCOMMIT();
#pragma unroll
            for (int p = 0; p < 2; p++) {
                const float* src = A + (size_t)(m0 + r0a + p * 64) * DM + k0 + c0a * 8;
                areg[p][0] = ((const float4*)src)[0];
                areg[p][1] = ((const float4*)src)[1];
            }
        }
#pragma unroll
        for (int ks = 0; ks < 2; ks++) {
            uint32_t ah[4][4], bh[4][2];
            const uint32_t aoff = (uint32_t)((lane & 15) * 80 +
                                  (ks * 16 + (lane >> 4) * 8) * 2) + so;
#pragma unroll
            for (int mb = 0; mb < 4; mb++)
                ldsm4(ah[mb], SAH + (uint32_t)(wm + mb * 16) * 80u + aoff);
            // B: x4 over 16 rows (2 nb blocks); lanes 16-31 -> +8 rows
            const uint32_t boff = (uint32_t)(((lane >> 4) & 1) * 8 * 80 +
                                  (lane & 7) * 80 +
                                  (ks * 16 + ((lane >> 3) & 1) * 8) * 2) + so;
#pragma unroll
            for (int nbp = 0; nbp < 2; nbp++) {
                uint32_t t[4];
                ldsm4(t, SBH + (uint32_t)(wn + nbp * 16) * 80u + boff);
                bh[2 * nbp][0] = t[0];     bh[2 * nbp][1] = t[1];
                bh[2 * nbp + 1][0] = t[2]; bh[2 * nbp + 1][1] = t[3];
            }
#pragma unroll
            for (int mb = 0; mb < 4; mb++)
#pragma unroll
                for (int nb = 0; nb < 4; nb++)
                    mma16816(acc[mb][nb], ah[mb], bh[nb]);
        }
    }
    __syncthreads();   // before epilogue reuses smem (V path)

    const int lr = lane >> 2, lc = (lane & 3) * 2;
    if (z != 2) {
        const float sc = (z == 0) ? 0.125f : 1.0f;
#pragma unroll
        for (int mb = 0; mb < 4; mb++) {
#pragma unroll
            for (int nb = 0; nb < 4; nb++) {
                const int col = n0 + wn + nb * 8 + lc;
                const float b0 = bias[col], b1 = bias[col + 1];
#pragma unroll
                for (int half_ = 0; half_ < 2; half_++) {
                    const int row = m0 + wm + mb * 16 + lr + 8 * half_;
                    const float v0 = (acc[mb][nb][2 * half_] + b0) * sc;
                    const float v1 = (acc[mb][nb][2 * half_ + 1] + b1) * sc;
                    const int bb = row >> 11, ss = row & (S_LEN - 1);
                    const int h = col >> 6, d = col & 63;
                    const size_t base = (((size_t)(bb * NH + h) * S_LEN + ss) << 6) + d;
                    *(uint32_t*)(Oh + base) = pcvt2(v0, v1);
                }
            }
        }
    } else {
        __half* tsm = (__half*)smc;   // [128 cols][TPAD]
#pragma unroll
        for (int mb = 0; mb < 4; mb++) {
#pragma unroll
            for (int nb = 0; nb < 4; nb++) {
                const int col = wn + nb * 8 + lc;
                const float b0 = bias[n0 + col], b1 = bias[n0 + col + 1];
#pragma unroll
                for (int half_ = 0; half_ < 2; half_++) {
                    const int row = wm + mb * 16 + lr + 8 * half_;
                    tsm[(size_t)col * TPAD + row] =
                        __float2half_rn(acc[mb][nb][2 * half_] + b0);
                    tsm[(size_t)(col + 1) * TPAD + row] =
                        __float2half_rn(acc[mb][nb][2 * half_ + 1] + b1);
                }
            }
        }
        __syncthreads();
        const int dl = tid >> 1;
        const int tof = (tid & 1) * 64;
        const int bb = m0 >> 11, ss0 = (m0 & (S_LEN - 1)) + tof;
        const int n = n0 + dl, h = n >> 6, d = n & 63;
        __half* dst = Oh + ((size_t)(bb * NH + h) * DK + d) * S_LEN + ss0;
        const __half* srcr = tsm + (size_t)dl * TPAD + tof;
#pragma unroll
        for (int j = 0; j < 8; j++)
            ((uint4*)dst)[j] = ((const uint4*)srcr)[j];
    }
}

// ---------------------------------------------------------------------------
// Output projection GEMM: single-sync pipeline, B ldsm4-merged.
// ---------------------------------------------------------------------------
__global__ __launch_bounds__(256, 2) void gemm_o_kernel(
    const __half* __restrict__ Ah, const __half* __restrict__ Bh,
    const float* __restrict__ bias, float* __restrict__ Of)
{
    extern __shared__ char smc[];
    const uint32_t smb = smem_u32(smc);
    const int tid = threadIdx.x, lane = tid & 31, wid = tid >> 5;
    const int m0 = blockIdx.y * 128, n0 = blockIdx.x * 128;
    const int wm = (wid >> 2) * 64, wn = (wid & 3) * 32;
    const uint32_t SAH = smb, SBH = smb + 2 * G_STAGE;

#pragma unroll
    for (int p = 0; p < 2; p++) {
        const int idx = tid + p * 256, r = idx >> 2, c = idx & 3;
        const uint32_t d = (uint32_t)r * 80u + (uint32_t)c * 16u;
        CP16(SAH + d, Ah + (size_t)(m0 + r) * DM + c * 8);
        CP16(SBH + d, Bh + (size_t)(n0 + r) * DM + c * 8);
    }
    CPCOMMIT();

    float acc[4][4][4];
#pragma unroll
    for (int a = 0; a < 4; a++)
#pragma unroll
        for (int b = 0; b < 4; b++)
#pragma unroll
            for (int c = 0; c < 4; c++) acc[a][b][c] = 0.f;

    for (int ch = 0; ch < 32; ch++) {
        CPWAIT0();
        __syncthreads();
        if (ch + 1 < 32) {
            const int k0 = (ch + 1) * 32;
            const uint32_t sn = (uint32_t)((ch + 1) & 1) * G_STAGE;
#pragma unroll
            for (int p = 0; p < 2; p++) {
                const int idx = tid + p * 256, r = idx >> 2, c = idx & 3;
                const uint32_t d = (uint32_t)r * 80u + (uint32_t)c * 16u + sn;
                CP16(SAH + d, Ah + (size_t)(m0 + r) * DM + k0 + c * 8);
                CP16(SBH + d, Bh + (size_t)(n0 + r) * DM + k0 + c * 8);
            }
            CPCOMMIT();
        }
        const uint32_t so = (uint32_t)(ch & 1) * G_STAGE;
#pragma unroll
        for (int ks = 0; ks < 2; ks++) {
            uint32_t ah[4][4], bh[4][2];
            const uint32_t aoff = (uint32_t)((lane & 15) * 80 +
                                  (ks * 16 + (lane >> 4) * 8) * 2) + so;
#pragma unroll
            for (int mb = 0; mb < 4; mb++)
                ldsm4(ah[mb], SAH + (uint32_t)(wm + mb * 16) * 80u + aoff);
            const uint32_t boff = (uint32_t)(((lane >> 4) & 1) * 8 * 80 +
                                  (lane & 7) * 80 +
                                  (ks * 16 + ((lane >> 3) & 1) * 8) * 2) + so;
#pragma unroll
            for (int nbp = 0; nbp < 2; nbp++) {
                uint32_t t[4];
                ldsm4(t, SBH + (uint32_t)(wn + nbp * 16) * 80u + boff);
                bh[2 * nbp][0] = t[0];     bh[2 * nbp][1] = t[1];
                bh[2 * nbp + 1][0] = t[2]; bh[2 * nbp + 1][1] = t[3];
            }
#pragma unroll
            for (int mb = 0; mb < 4; mb++)
#pragma unroll
                for (int nb = 0; nb < 4; nb++)
                    mma16816(acc[mb][nb], ah[mb], bh[nb]);
        }
    }

    const int lr = lane >> 2, lc = (lane & 3) * 2;
#pragma unroll
    for (int mb = 0; mb < 4; mb++) {
#pragma unroll
        for (int nb = 0; nb < 4; nb++) {
            const int col = n0 + wn + nb * 8 + lc;
            const float b0 = bias[col], b1 = bias[col + 1];
#pragma unroll
            for (int half_ = 0; half_ < 2; half_++) {
                const int row = m0 + wm + mb * 16 + lr + 8 * half_;
                *(float2*)(Of + (size_t)row * DM + col) =
                    make_float2(acc[mb][nb][2 * half_] + b0,
                                acc[mb][nb][2 * half_ + 1] + b1);
            }
        }
    }
}

// ---------------------------------------------------------------------------
// Flash attention: single-sync pipeline, K/V ldsm4-merged.
// ---------------------------------------------------------------------------
#define AP 72                     // 144B rows: conflict-free
#define A_QBYTES (128 * AP * 2)
#define A_STAGE  (64 * AP * 2)
#define A_SMEM   (A_QBYTES + 4 * A_STAGE)

__global__ __launch_bounds__(256, 2) void attn_mma_kernel(
    const __half* __restrict__ Qh, const __half* __restrict__ Kh,
    const __half* __restrict__ Vth, __half* __restrict__ AO)
{
    extern __shared__ char smc[];
    const uint32_t smb = smem_u32(smc);
    const int tid = threadIdx.x, lane = tid & 31, wid = tid >> 5;
    const int bh = blockIdx.y;
    const int q0 = blockIdx.x * 128;
    const uint32_t SQH = smb;
    const uint32_t SKH = smb + A_QBYTES, SVH = SKH + 2 * A_STAGE;

    const size_t qbase = ((size_t)bh * S_LEN + q0) * DK;
    const size_t kbase = (size_t)bh * S_LEN * DK;
    const size_t vbase = (size_t)bh * DK * S_LEN;

    {
#pragma unroll
        for (int p = 0; p < 4; p++) {
            const int idx = tid + p * 256, r = idx >> 3, c = idx & 7;
            CP16(SQH + (uint32_t)r * 144u + (uint32_t)c * 16u,
                 Qh + qbase + (size_t)r * DK + c * 8);
        }
#pragma unroll
        for (int p = 0; p < 2; p++) {
            const int idx = tid + p * 256, r = idx >> 3, c = idx & 7;
            const uint32_t d = (uint32_t)r * 144u + (uint32_t)c * 16u;
            CP16(SKH + d, Kh + kbase + (size_t)r * DK + c * 8);
            CP16(SVH + d, Vth + vbase + (size_t)r * S_LEN + c * 8);
        }
        CPCOMMIT();
    }

    const int r0 = wid * 16;
    float oacc[8][4];
    float lsum[2] = {0.f, 0.f};
#pragma unroll
    for (int db = 0; db < 8; db++)
#pragma unroll
        for (int e = 0; e < 4; e++) oacc[db][e] = 0.f;

    for (int i = 0; i < 32; i++) {
        CPWAIT0();
        __syncthreads();
        if (i + 1 < 32) {
            const int t0 = (i + 1) * 64;
            const uint32_t sn = (uint32_t)((i + 1) & 1) * A_STAGE;
#pragma unroll
            for (int p = 0; p < 2; p++) {
                const int idx = tid + p * 256, r = idx >> 3, c = idx & 7;
                const uint32_t d = (uint32_t)r * 144u + (uint32_t)c * 16u + sn;
                CP16(SKH + d, Kh + kbase + (size_t)(t0 + r) * DK + c * 8);
                CP16(SVH + d, Vth + vbase + (size_t)r * S_LEN + t0 + c * 8);
            }
            CPCOMMIT();
        }
        const uint32_t so = (uint32_t)(i & 1) * A_STAGE;

        // ---- MMA1: S[16 x 64] = Q @ K^T ----
        float sacc[8][4];
#pragma unroll
        for (int nb = 0; nb < 8; nb++)
#pragma unroll
            for (int e = 0; e < 4; e++) sacc[nb][e] = 0.f;
#pragma unroll
        for (int ks = 0; ks < 4; ks++) {
            uint32_t qf[4];
            ldsm4(qf, SQH + (uint32_t)((r0 + (lane & 15)) * 144 +
                                       (ks * 16 + (lane >> 4) * 8) * 2));
            const uint32_t bo = (uint32_t)(((lane >> 4) & 1) * 8 * 144 +
                                 (lane & 7) * 144 +
                                 (ks * 16 + ((lane >> 3) & 1) * 8) * 2) + so;
#pragma unroll
            for (int nbp = 0; nbp < 4; nbp++) {
                uint32_t t[4];
                ldsm4(t, SKH + (uint32_t)(nbp * 16) * 144u + bo);
                mma16816(sacc[2 * nbp],     qf, t);
                mma16816(sacc[2 * nbp + 1], qf, t + 2);
            }
        }

        // ---- exp + row-sum partials ----
#pragma unroll
        for (int nb = 0; nb < 8; nb++)
#pragma unroll
            for (int e = 0; e < 4; e++) {
                const float p = __expf(sacc[nb][e]);
                lsum[e >> 1] += p;
                sacc[nb][e] = p;
            }

        // ---- MMA2: O += P @ Vh ----
#pragma unroll
        for (int ts = 0; ts < 4; ts++) {
            uint32_t ph[4];
            ph[0] = pcvt2(sacc[2 * ts][0],     sacc[2 * ts][1]);
            ph[1] = pcvt2(sacc[2 * ts][2],     sacc[2 * ts][3]);
            ph[2] = pcvt2(sacc[2 * ts + 1][0], sacc[2 * ts + 1][1]);
            ph[3] = pcvt2(sacc[2 * ts + 1][2], sacc[2 * ts + 1][3]);
            const uint32_t vo = (uint32_t)(((lane >> 4) & 1) * 8 * 144 +
                                 (lane & 7) * 144 +
                                 (ts * 16 + ((lane >> 3) & 1) * 8) * 2) + so;
#pragma unroll
            for (int dbp = 0; dbp < 4; dbp++) {
                uint32_t t[4];
                ldsm4(t, SVH + (uint32_t)(dbp * 16) * 144u + vo);
                mma16816(oacc[2 * dbp],     ph, t);
                mma16816(oacc[2 * dbp + 1], ph, t + 2);
            }
        }
    }

#pragma unroll
    for (int e = 0; e < 2; e++) {
        lsum[e] += __shfl_xor_sync(0xffffffffu, lsum[e], 1);
        lsum[e] += __shfl_xor_sync(0xffffffffu, lsum[e], 2);
    }
    const float inv0 = 1.f / lsum[0], inv1 = 1.f / lsum[1];

    const int bb = bh >> 4, hh = bh & 15;
    const int rowa = q0 + r0 + (lane >> 2);
#pragma unroll
    for (int db = 0; db < 8; db++) {
        const int col = hh * 64 + db * 8 + (lane & 3) * 2;
        const size_t ba = ((size_t)bb * S_LEN + rowa) * DM + col;
        const size_t bb2 = ba + (size_t)8 * DM;
        *(uint32_t*)(AO + ba)  = pcvt2(oacc[db][0] * inv0, oacc[db][1] * inv0);
        *(uint32_t*)(AO + bb2) = pcvt2(oacc[db][2] * inv1, oacc[db][3] * inv1);
    }
}

// ---------------------------------------------------------------------------
extern "C" void kernel_launch(void* const* d_in, const int* in_sizes, int n_in,
                              void* d_out, int out_size)
{
    const float* q  = (const float*)d_in[0];
    const float* k  = (const float*)d_in[1];
    const float* v  = (const float*)d_in[2];
    const float* Wq = (const float*)d_in[3];
    const float* bq = (const float*)d_in[4];
    const float* Wk = (const float*)d_in[5];
    const float* bk = (const float*)d_in[6];
    const float* Wv = (const float*)d_in[7];
    const float* bv = (const float*)d_in[8];
    const float* Wo = (const float*)d_in[9];
    const float* bo = (const float*)d_in[10];
    float* out = (float*)d_out;

    __half *qh, *kh, *vt, *at, *wq, *wk, *wv, *wo;
    cudaGetSymbolAddress((void**)&qh, g_q);
    cudaGetSymbolAddress((void**)&kh, g_k);
    cudaGetSymbolAddress((void**)&vt, g_vt);
    cudaGetSymbolAddress((void**)&at, g_at);
    cudaGetSymbolAddress((void**)&wq, g_wq);
    cudaGetSymbolAddress((void**)&wk, g_wk);
    cudaGetSymbolAddress((void**)&wv, g_wv);
    cudaGetSymbolAddress((void**)&wo, g_wo);

    cudaFuncSetAttribute(gemm_qkv_kernel, cudaFuncAttributeMaxDynamicSharedMemorySize, G_SMEM);
    cudaFuncSetAttribute(gemm_o_kernel, cudaFuncAttributeMaxDynamicSharedMemorySize, G_SMEM);
    cudaFuncSetAttribute(attn_mma_kernel, cudaFuncAttributeMaxDynamicSharedMemorySize, A_SMEM);

    dim3 wg(32, 32, 4);
    wsplit_kernel<<<wg, 256>>>(Wq, Wk, Wv, Wo, wq, wk, wv, wo);

    dim3 gqkv(DM / 128, MROWS / 128, 3);
    gemm_qkv_kernel<<<gqkv, 256, G_SMEM>>>(q, k, v, wq, wk, wv, bq, bk, bv,
                                           qh, kh, vt);

    dim3 ga(S_LEN / 128, NB * NH);
    attn_mma_kernel<<<ga, 256, A_SMEM>>>(qh, kh, vt, at);

    dim3 gg(DM / 128, MROWS / 128);
    gemm_o_kernel<<<gg, 256, G_SMEM>>>(at, wo, bo, out);
}

// round 13
// speedup vs baseline: 1.8041x; 1.0186x over previous
#include <cuda_runtime.h>
#include <cuda_fp16.h>
#include <cstdint>

#define S_LEN 2048
#define NB 2
#define NH 16
#define DK 64
#define DM 1024
#define MROWS (NB * S_LEN)   // 4096
#define HEADELEMS ((size_t)NB * NH * S_LEN * DK)

// ---------------- scratch (__device__ globals; no allocs allowed) ----------
__device__ __half g_q[HEADELEMS];                        // [b,h][t][d], 1/8 folded
__device__ __half g_k[HEADELEMS];                        // [b,h][t][d]
__device__ __half g_vt[HEADELEMS];                       // [b,h][d][t]
__device__ __half g_at[(size_t)MROWS * DM];              // attention out [b][s][h*64+d]
__device__ __half g_wq[DM * DM], g_wk[DM * DM], g_wv[DM * DM], g_wo[DM * DM];

// ---------------- PTX helpers ----------------------------------------------
__device__ __forceinline__ uint32_t smem_u32(const void* p) {
    uint32_t a;
    asm("{ .reg .u64 t; cvta.to.shared.u64 t, %1; cvt.u32.u64 %0, t; }" : "=r"(a) : "l"(p));
    return a;
}
#define CP16(dst, src) asm volatile("cp.async.ca.shared.global [%0], [%1], 16;" :: "r"(dst), "l"(src))
#define CPCOMMIT()     asm volatile("cp.async.commit_group;" ::: "memory")
#define CPWAIT0()      asm volatile("cp.async.wait_group 0;" ::: "memory")

__device__ __forceinline__ void ldsm4(uint32_t* r, uint32_t a) {
    asm volatile("ldmatrix.sync.aligned.m8n8.x4.shared.b16 {%0,%1,%2,%3}, [%4];"
                 : "=r"(r[0]), "=r"(r[1]), "=r"(r[2]), "=r"(r[3]) : "r"(a));
}
__device__ __forceinline__ void mma16816(float* d, const uint32_t* a, const uint32_t* b) {
    asm volatile("mma.sync.aligned.m16n8k16.row.col.f32.f16.f16.f32 "
                 "{%0,%1,%2,%3},{%4,%5,%6,%7},{%8,%9},{%0,%1,%2,%3};"
                 : "+f"(d[0]), "+f"(d[1]), "+f"(d[2]), "+f"(d[3])
                 : "r"(a[0]), "r"(a[1]), "r"(a[2]), "r"(a[3]), "r"(b[0]), "r"(b[1]));
}

__device__ __forceinline__ uint32_t pack2(uint16_t a, uint16_t b) {
    return (uint32_t)a | ((uint32_t)b << 16);
}
__device__ __forceinline__ uint32_t pcvt2(float x, float y) {
    return pack2(__half_as_ushort(__float2half_rn(x)),
                 __half_as_ushort(__float2half_rn(y)));
}

// ---------------------------------------------------------------------------
// Fused weight transpose + convert (z selects which W):  T[n][k] = fp16(W[k][n])
// ---------------------------------------------------------------------------
__global__ __launch_bounds__(256) void wsplit_kernel(
    const float* __restrict__ W0, const float* __restrict__ W1,
    const float* __restrict__ W2, const float* __restrict__ W3,
    __half* __restrict__ T0, __half* __restrict__ T1,
    __half* __restrict__ T2, __half* __restrict__ T3)
{
    const int z = blockIdx.z;
    const float* W = (z == 0) ? W0 : (z == 1) ? W1 : (z == 2) ? W2 : W3;
    __half* Th     = (z == 0) ? T0 : (z == 1) ? T1 : (z == 2) ? T2 : T3;

    __shared__ float ts[32][33];
    const int tid = threadIdx.x;
    const int tx = tid & 31, ty = tid >> 5;
    const int k0 = blockIdx.x * 32, n0 = blockIdx.y * 32;
#pragma unroll
    for (int p = 0; p < 4; p++)
        ts[ty + 8 * p][tx] = W[(size_t)(k0 + ty + 8 * p) * DM + n0 + tx];
    __syncthreads();
#pragma unroll
    for (int p = 0; p < 4; p++) {
        const int r = ty + 8 * p;
        Th[(size_t)(n0 + r) * DM + k0 + tx] = __float2half_rn(ts[tx][r]);
    }
}

// ---------------------------------------------------------------------------
// Fused QKV GEMM (unchanged from R12): single-sync pipeline, B ldsm4-merged.
// ---------------------------------------------------------------------------
#define GP 40                   // 80B row stride
#define G_STAGE (128 * GP * 2)  // 10240 bytes
#define G_SMEM  (4 * G_STAGE)   // 40960 (also >= 128*136*2 V-bounce)
#define TPAD 136

__global__ __launch_bounds__(256, 2) void gemm_qkv_kernel(
    const float* __restrict__ A0, const float* __restrict__ A1,
    const float* __restrict__ A2,
    const __half* __restrict__ B0, const __half* __restrict__ B1,
    const __half* __restrict__ B2,
    const float* __restrict__ bias0, const float* __restrict__ bias1,
    const float* __restrict__ bias2,
    __half* __restrict__ O0, __half* __restrict__ O1, __half* __restrict__ O2)
{
    extern __shared__ char smc[];
    const uint32_t smb = smem_u32(smc);
    const int z = blockIdx.z;
    const float*  A    = (z == 0) ? A0 : (z == 1) ? A1 : A2;
    const __half* Bh   = (z == 0) ? B0 : (z == 1) ? B1 : B2;
    const float*  bias = (z == 0) ? bias0 : (z == 1) ? bias1 : bias2;
    __half* Oh         = (z == 0) ? O0 : (z == 1) ? O1 : O2;

    const int tid = threadIdx.x, lane = tid & 31, wid = tid >> 5;
    const int m0 = blockIdx.y * 128, n0 = blockIdx.x * 128;
    const int wm = (wid >> 2) * 64, wn = (wid & 3) * 32;
    const uint32_t SAH = smb, SBH = smb + 2 * G_STAGE;

    const int r0a = tid >> 2, c0a = tid & 3;

    float4 areg[2][2];
#pragma unroll
    for (int p = 0; p < 2; p++) {
        const float* src = A + (size_t)(m0 + r0a + p * 64) * DM + c0a * 8;
        areg[p][0] = ((const float4*)src)[0];
        areg[p][1] = ((const float4*)src)[1];
    }
#pragma unroll
    for (int p = 0; p < 2; p++) {
        const int idx = tid + p * 256, r = idx >> 2, c = idx & 3;
        CP16(SBH + (uint32_t)r * 80u + (uint32_t)c * 16u,
             Bh + (size_t)(n0 + r) * DM + c * 8);
    }
    CPCOMMIT();

    float acc[4][4][4];
#pragma unroll
    for (int a = 0; a < 4; a++)
#pragma unroll
        for (int b = 0; b < 4; b++)
#pragma unroll
            for (int c = 0; c < 4; c++) acc[a][b][c] = 0.f;

    for (int ch = 0; ch < 32; ch++) {
        const uint32_t so = (uint32_t)(ch & 1) * G_STAGE;
#pragma unroll
        for (int p = 0; p < 2; p++) {
            uint4 v;
            v.x = pcvt2(areg[p][0].x, areg[p][0].y);
            v.y = pcvt2(areg[p][0].z, areg[p][0].w);
            v.z = pcvt2(areg[p][1].x, areg[p][1].y);
            v.w = pcvt2(areg[p][1].z, areg[p][1].w);
            *(uint4*)(smc + (uint32_t)(r0a + p * 64) * 80u +
                      (uint32_t)c0a * 16u + so) = v;
        }
        CPWAIT0();
        __syncthreads();
        if (ch + 1 < 32) {
            const int k0 = (ch + 1) * 32;
            const uint32_t sn = (uint32_t)((ch + 1) & 1) * G_STAGE;
#pragma unroll
            for (int p = 0; p < 2; p++) {
                const int idx = tid + p * 256, r = idx >> 2, c = idx & 3;
                CP16(SBH + (uint32_t)r * 80u + (uint32_t)c * 16u + sn,
                     Bh + (size_t)(n0 + r) * DM + k0 + c * 8);
            }
            CPCOMMIT();
#pragma unroll
            for (int p = 0; p < 2; p++) {
                const float* src = A + (size_t)(m0 + r0a + p * 64) * DM + k0 + c0a * 8;
                areg[p][0] = ((const float4*)src)[0];
                areg[p][1] = ((const float4*)src)[1];
            }
        }
#pragma unroll
        for (int ks = 0; ks < 2; ks++) {
            uint32_t ah[4][4], bh[4][2];
            const uint32_t aoff = (uint32_t)((lane & 15) * 80 +
                                  (ks * 16 + (lane >> 4) * 8) * 2) + so;
#pragma unroll
            for (int mb = 0; mb < 4; mb++)
                ldsm4(ah[mb], SAH + (uint32_t)(wm + mb * 16) * 80u + aoff);
            const uint32_t boff = (uint32_t)(((lane >> 4) & 1) * 8 * 80 +
                                  (lane & 7) * 80 +
                                  (ks * 16 + ((lane >> 3) & 1) * 8) * 2) + so;
#pragma unroll
            for (int nbp = 0; nbp < 2; nbp++) {
                uint32_t t[4];
                ldsm4(t, SBH + (uint32_t)(wn + nbp * 16) * 80u + boff);
                bh[2 * nbp][0] = t[0];     bh[2 * nbp][1] = t[1];
                bh[2 * nbp + 1][0] = t[2]; bh[2 * nbp + 1][1] = t[3];
            }
#pragma unroll
            for (int mb = 0; mb < 4; mb++)
#pragma unroll
                for (int nb = 0; nb < 4; nb++)
                    mma16816(acc[mb][nb], ah[mb], bh[nb]);
        }
    }
    __syncthreads();

    const int lr = lane >> 2, lc = (lane & 3) * 2;
    if (z != 2) {
        const float sc = (z == 0) ? 0.125f : 1.0f;
#pragma unroll
        for (int mb = 0; mb < 4; mb++) {
#pragma unroll
            for (int nb = 0; nb < 4; nb++) {
                const int col = n0 + wn + nb * 8 + lc;
                const float b0 = bias[col], b1 = bias[col + 1];
#pragma unroll
                for (int half_ = 0; half_ < 2; half_++) {
                    const int row = m0 + wm + mb * 16 + lr + 8 * half_;
                    const float v0 = (acc[mb][nb][2 * half_] + b0) * sc;
                    const float v1 = (acc[mb][nb][2 * half_ + 1] + b1) * sc;
                    const int bb = row >> 11, ss = row & (S_LEN - 1);
                    const int h = col >> 6, d = col & 63;
                    const size_t base = (((size_t)(bb * NH + h) * S_LEN + ss) << 6) + d;
                    *(uint32_t*)(Oh + base) = pcvt2(v0, v1);
                }
            }
        }
    } else {
        __half* tsm = (__half*)smc;
#pragma unroll
        for (int mb = 0; mb < 4; mb++) {
#pragma unroll
            for (int nb = 0; nb < 4; nb++) {
                const int col = wn + nb * 8 + lc;
                const float b0 = bias[n0 + col], b1 = bias[n0 + col + 1];
#pragma unroll
                for (int half_ = 0; half_ < 2; half_++) {
                    const int row = wm + mb * 16 + lr + 8 * half_;
                    tsm[(size_t)col * TPAD + row] =
                        __float2half_rn(acc[mb][nb][2 * half_] + b0);
                    tsm[(size_t)(col + 1) * TPAD + row] =
                        __float2half_rn(acc[mb][nb][2 * half_ + 1] + b1);
                }
            }
        }
        __syncthreads();
        const int dl = tid >> 1;
        const int tof = (tid & 1) * 64;
        const int bb = m0 >> 11, ss0 = (m0 & (S_LEN - 1)) + tof;
        const int n = n0 + dl, h = n >> 6, d = n & 63;
        __half* dst = Oh + ((size_t)(bb * NH + h) * DK + d) * S_LEN + ss0;
        const __half* srcr = tsm + (size_t)dl * TPAD + tof;
#pragma unroll
        for (int j = 0; j < 8; j++)
            ((uint4*)dst)[j] = ((const uint4*)srcr)[j];
    }
}

// ---------------------------------------------------------------------------
// Output projection GEMM: K macro-chunk 64 (4 k16 steps per sync), 144B rows.
// ---------------------------------------------------------------------------
#define O_ST 18432              // stage bytes: 128 rows x 144B
#define O_SMEM (4 * O_ST)       // A 2-stage + B 2-stage = 73728

__global__ __launch_bounds__(256, 2) void gemm_o_kernel(
    const __half* __restrict__ Ah, const __half* __restrict__ Bh,
    const float* __restrict__ bias, float* __restrict__ Of)
{
    extern __shared__ char smc[];
    const uint32_t smb = smem_u32(smc);
    const int tid = threadIdx.x, lane = tid & 31, wid = tid >> 5;
    const int m0 = blockIdx.y * 128, n0 = blockIdx.x * 128;
    const int wm = (wid >> 2) * 64, wn = (wid & 3) * 32;
    const uint32_t SAH = smb, SBH = smb + 2 * O_ST;

    // prologue: chunk 0 (64 k-cols = 8 x16B per row; 1024 segs per array)
#pragma unroll
    for (int p = 0; p < 4; p++) {
        const int idx = tid + p * 256, r = idx >> 3, c = idx & 7;
        const uint32_t d = (uint32_t)r * 144u + (uint32_t)c * 16u;
        CP16(SAH + d, Ah + (size_t)(m0 + r) * DM + c * 8);
        CP16(SBH + d, Bh + (size_t)(n0 + r) * DM + c * 8);
    }
    CPCOMMIT();

    float acc[4][4][4];
#pragma unroll
    for (int a = 0; a < 4; a++)
#pragma unroll
        for (int b = 0; b < 4; b++)
#pragma unroll
            for (int c = 0; c < 4; c++) acc[a][b][c] = 0.f;

    CPWAIT0();
    __syncthreads();

    for (int ch = 0; ch < 16; ch++) {
        if (ch > 0) { CPWAIT0(); __syncthreads(); }
        if (ch + 1 < 16) {
            const int k0 = (ch + 1) * 64;
            const uint32_t sn = (uint32_t)((ch + 1) & 1) * O_ST;
#pragma unroll
            for (int p = 0; p < 4; p++) {
                const int idx = tid + p * 256, r = idx >> 3, c = idx & 7;
                const uint32_t d = (uint32_t)r * 144u + (uint32_t)c * 16u + sn;
                CP16(SAH + d, Ah + (size_t)(m0 + r) * DM + k0 + c * 8);
                CP16(SBH + d, Bh + (size_t)(n0 + r) * DM + k0 + c * 8);
            }
            CPCOMMIT();
        }
        const uint32_t so = (uint32_t)(ch & 1) * O_ST;
#pragma unroll
        for (int ks = 0; ks < 4; ks++) {
            uint32_t ah[4][4], bh[4][2];
            const uint32_t aoff = (uint32_t)((lane & 15) * 144 +
                                  (ks * 16 + (lane >> 4) * 8) * 2) + so;
#pragma unroll
            for (int mb = 0; mb < 4; mb++)
                ldsm4(ah[mb], SAH + (uint32_t)(wm + mb * 16) * 144u + aoff);
            const uint32_t boff = (uint32_t)(((lane >> 4) & 1) * 8 * 144 +
                                  (lane & 7) * 144 +
                                  (ks * 16 + ((lane >> 3) & 1) * 8) * 2) + so;
#pragma unroll
            for (int nbp = 0; nbp < 2; nbp++) {
                uint32_t t[4];
                ldsm4(t, SBH + (uint32_t)(wn + nbp * 16) * 144u + boff);
                bh[2 * nbp][0] = t[0];     bh[2 * nbp][1] = t[1];
                bh[2 * nbp + 1][0] = t[2]; bh[2 * nbp + 1][1] = t[3];
            }
#pragma unroll
            for (int mb = 0; mb < 4; mb++)
#pragma unroll
                for (int nb = 0; nb < 4; nb++)
                    mma16816(acc[mb][nb], ah[mb], bh[nb]);
        }
    }

    const int lr = lane >> 2, lc = (lane & 3) * 2;
#pragma unroll
    for (int mb = 0; mb < 4; mb++) {
#pragma unroll
        for (int nb = 0; nb < 4; nb++) {
            const int col = n0 + wn + nb * 8 + lc;
            const float b0 = bias[col], b1 = bias[col + 1];
#pragma unroll
            for (int half_ = 0; half_ < 2; half_++) {
                const int row = m0 + wm + mb * 16 + lr + 8 * half_;
                *(float2*)(Of + (size_t)row * DM + col) =
                    make_float2(acc[mb][nb][2 * half_] + b0,
                                acc[mb][nb][2 * half_ + 1] + b1);
            }
        }
    }
}

// ---------------------------------------------------------------------------
// Flash attention: KV macro-chunk 128 = 2x64 halves per sync; Q frags hoisted.
// K stages: 128 rows x 144B.  V stages: 64 rows x 272B (both conflict-free).
// ---------------------------------------------------------------------------
#define AK_ST 18432               // K stage: 128 x 144
#define AV_ST 17408               // V stage: 64 x 272
#define A_QB  18432               // Q: 128 x 144
#define A_SMEM (A_QB + 2 * AK_ST + 2 * AV_ST)   // 90112

__global__ __launch_bounds__(256, 2) void attn_mma_kernel(
    const __half* __restrict__ Qh, const __half* __restrict__ Kh,
    const __half* __restrict__ Vth, __half* __restrict__ AO)
{
    extern __shared__ char smc[];
    const uint32_t smb = smem_u32(smc);
    const int tid = threadIdx.x, lane = tid & 31, wid = tid >> 5;
    const int bh = blockIdx.y;
    const int q0 = blockIdx.x * 128;
    const uint32_t SQH = smb;
    const uint32_t SKH = smb + A_QB, SVH = SKH + 2 * AK_ST;

    const size_t qbase = ((size_t)bh * S_LEN + q0) * DK;
    const size_t kbase = (size_t)bh * S_LEN * DK;
    const size_t vbase = (size_t)bh * DK * S_LEN;

    // prologue: Q + K,V chunk 0 (128 t each)
    {
#pragma unroll
        for (int p = 0; p < 4; p++) {
            const int idx = tid + p * 256, r = idx >> 3, c = idx & 7;
            CP16(SQH + (uint32_t)r * 144u + (uint32_t)c * 16u,
                 Qh + qbase + (size_t)r * DK + c * 8);
            CP16(SKH + (uint32_t)r * 144u + (uint32_t)c * 16u,
                 Kh + kbase + (size_t)r * DK + c * 8);
        }
#pragma unroll
        for (int p = 0; p < 4; p++) {
            const int idx = tid + p * 256, r = idx >> 4, c = idx & 15;  // 64 x 16
            CP16(SVH + (uint32_t)r * 272u + (uint32_t)c * 16u,
                 Vth + vbase + (size_t)r * S_LEN + c * 8);
        }
        CPCOMMIT();
    }

    const int r0 = wid * 16;
    float oacc[8][4];
    float lsum[2] = {0.f, 0.f};
#pragma unroll
    for (int db = 0; db < 8; db++)
#pragma unroll
        for (int e = 0; e < 4; e++) oacc[db][e] = 0.f;

    CPWAIT0();
    __syncthreads();

    // hoist Q fragments (invariant across all KV chunks)
    uint32_t qf_all[4][4];
#pragma unroll
    for (int ks = 0; ks < 4; ks++)
        ldsm4(qf_all[ks], SQH + (uint32_t)((r0 + (lane & 15)) * 144 +
                                           (ks * 16 + (lane >> 4) * 8) * 2));

    for (int i = 0; i < 16; i++) {
        if (i > 0) { CPWAIT0(); __syncthreads(); }
        if (i + 1 < 16) {
            const int t0 = (i + 1) * 128;
            const uint32_t skn = (uint32_t)((i + 1) & 1) * AK_ST;
            const uint32_t svn = (uint32_t)((i + 1) & 1) * AV_ST;
#pragma unroll
            for (int p = 0; p < 4; p++) {
                const int idx = tid + p * 256, r = idx >> 3, c = idx & 7;
                CP16(SKH + (uint32_t)r * 144u + (uint32_t)c * 16u + skn,
                     Kh + kbase + (size_t)(t0 + r) * DK + c * 8);
            }
#pragma unroll
            for (int p = 0; p < 4; p++) {
                const int idx = tid + p * 256, r = idx >> 4, c = idx & 15;
                CP16(SVH + (uint32_t)r * 272u + (uint32_t)c * 16u + svn,
                     Vth + vbase + (size_t)r * S_LEN + t0 + c * 8);
            }
            CPCOMMIT();
        }
        const uint32_t sk = (uint32_t)(i & 1) * AK_ST;
        const uint32_t sv = (uint32_t)(i & 1) * AV_ST;

#pragma unroll
        for (int hf = 0; hf < 2; hf++) {
            // ---- MMA1: S[16 x 64] = Q @ K^T (K rows hf*64 .. hf*64+63) ----
            float sacc[8][4];
#pragma unroll
            for (int nb = 0; nb < 8; nb++)
#pragma unroll
                for (int e = 0; e < 4; e++) sacc[nb][e] = 0.f;
            const uint32_t kbs = SKH + sk + (uint32_t)(hf * 64) * 144u;
#pragma unroll
            for (int ks = 0; ks < 4; ks++) {
                const uint32_t bo = (uint32_t)(((lane >> 4) & 1) * 8 * 144 +
                                     (lane & 7) * 144 +
                                     (ks * 16 + ((lane >> 3) & 1) * 8) * 2);
#pragma unroll
                for (int nbp = 0; nbp < 4; nbp++) {
                    uint32_t t[4];
                    ldsm4(t, kbs + (uint32_t)(nbp * 16) * 144u + bo);
                    mma16816(sacc[2 * nbp],     qf_all[ks], t);
                    mma16816(sacc[2 * nbp + 1], qf_all[ks], t + 2);
                }
            }

            // ---- exp + row-sum partials ----
#pragma unroll
            for (int nb = 0; nb < 8; nb++)
#pragma unroll
                for (int e = 0; e < 4; e++) {
                    const float p = __expf(sacc[nb][e]);
                    lsum[e >> 1] += p;
                    sacc[nb][e] = p;
                }

            // ---- MMA2: O += P @ Vh (V t-cols hf*64 ..) ----
            const uint32_t vbs = SVH + sv;
#pragma unroll
            for (int ts = 0; ts < 4; ts++) {
                uint32_t ph[4];
                ph[0] = pcvt2(sacc[2 * ts][0],     sacc[2 * ts][1]);
                ph[1] = pcvt2(sacc[2 * ts][2],     sacc[2 * ts][3]);
                ph[2] = pcvt2(sacc[2 * ts + 1][0], sacc[2 * ts + 1][1]);
                ph[3] = pcvt2(sacc[2 * ts + 1][2], sacc[2 * ts + 1][3]);
                const uint32_t vo = (uint32_t)(((lane >> 4) & 1) * 8 * 272 +
                                     (lane & 7) * 272 +
                                     (hf * 64 + ts * 16 + ((lane >> 3) & 1) * 8) * 2);
#pragma unroll
                for (int dbp = 0; dbp < 4; dbp++) {
                    uint32_t t[4];
                    ldsm4(t, vbs + (uint32_t)(dbp * 16) * 272u + vo);
                    mma16816(oacc[2 * dbp],     ph, t);
                    mma16816(oacc[2 * dbp + 1], ph, t + 2);
                }
            }
        }
    }

#pragma unroll
    for (int e = 0; e < 2; e++) {
        lsum[e] += __shfl_xor_sync(0xffffffffu, lsum[e], 1);
        lsum[e] += __shfl_xor_sync(0xffffffffu, lsum[e], 2);
    }
    const float inv0 = 1.f / lsum[0], inv1 = 1.f / lsum[1];

    const int bb = bh >> 4, hh = bh & 15;
    const int rowa = q0 + r0 + (lane >> 2);
#pragma unroll
    for (int db = 0; db < 8; db++) {
        const int col = hh * 64 + db * 8 + (lane & 3) * 2;
        const size_t ba = ((size_t)bb * S_LEN + rowa) * DM + col;
        const size_t bb2 = ba + (size_t)8 * DM;
        *(uint32_t*)(AO + ba)  = pcvt2(oacc[db][0] * inv0, oacc[db][1] * inv0);
        *(uint32_t*)(AO + bb2) = pcvt2(oacc[db][2] * inv1, oacc[db][3] * inv1);
    }
}

// ---------------------------------------------------------------------------
extern "C" void kernel_launch(void* const* d_in, const int* in_sizes, int n_in,
                              void* d_out, int out_size)
{
    const float* q  = (const float*)d_in[0];
    const float* k  = (const float*)d_in[1];
    const float* v  = (const float*)d_in[2];
    const float* Wq = (const float*)d_in[3];
    const float* bq = (const float*)d_in[4];
    const float* Wk = (const float*)d_in[5];
    const float* bk = (const float*)d_in[6];
    const float* Wv = (const float*)d_in[7];
    const float* bv = (const float*)d_in[8];
    const float* Wo = (const float*)d_in[9];
    const float* bo = (const float*)d_in[10];
    float* out = (float*)d_out;

    __half *qh, *kh, *vt, *at, *wq, *wk, *wv, *wo;
    cudaGetSymbolAddress((void**)&qh, g_q);
    cudaGetSymbolAddress((void**)&kh, g_k);
    cudaGetSymbolAddress((void**)&vt, g_vt);
    cudaGetSymbolAddress((void**)&at, g_at);
    cudaGetSymbolAddress((void**)&wq, g_wq);
    cudaGetSymbolAddress((void**)&wk, g_wk);
    cudaGetSymbolAddress((void**)&wv, g_wv);
    cudaGetSymbolAddress((void**)&wo, g_wo);

    cudaFuncSetAttribute(gemm_qkv_kernel, cudaFuncAttributeMaxDynamicSharedMemorySize, G_SMEM);
    cudaFuncSetAttribute(gemm_o_kernel, cudaFuncAttributeMaxDynamicSharedMemorySize, O_SMEM);
    cudaFuncSetAttribute(attn_mma_kernel, cudaFuncAttributeMaxDynamicSharedMemorySize, A_SMEM);

    dim3 wg(32, 32, 4);
    wsplit_kernel<<<wg, 256>>>(Wq, Wk, Wv, Wo, wq, wk, wv, wo);

    dim3 gqkv(DM / 128, MROWS / 128, 3);
    gemm_qkv_kernel<<<gqkv, 256, G_SMEM>>>(q, k, v, wq, wk, wv, bq, bk, bv,
                                           qh, kh, vt);

    dim3 ga(S_LEN / 128, NB * NH);
    attn_mma_kernel<<<ga, 256, A_SMEM>>>(qh, kh, vt, at);

    dim3 gg(DM / 128, MROWS / 128);
    gemm_o_kernel<<<gg, 256, O_SMEM>>>(at, wo, bo, out);
}

// round 14
// speedup vs baseline: 1.8212x; 1.0095x over previous
#include <cuda_runtime.h>
#include <cuda_fp16.h>
#include <cstdint>

#define S_LEN 2048
#define NB 2
#define NH 16
#define DK 64
#define DM 1024
#define MROWS (NB * S_LEN)   // 4096
#define HEADELEMS ((size_t)NB * NH * S_LEN * DK)

// ---------------- scratch (__device__ globals; no allocs allowed) ----------
__device__ __half g_q[HEADELEMS];                        // [b,h][t][d], 1/8 folded
__device__ __half g_k[HEADELEMS];                        // [b,h][t][d]
__device__ __half g_vt[HEADELEMS];                       // [b,h][d][t]
__device__ __half g_at[(size_t)MROWS * DM];              // attention out [b][s][h*64+d]
__device__ __half g_wq[DM * DM], g_wk[DM * DM], g_wv[DM * DM], g_wo[DM * DM];

// ---------------- PTX helpers ----------------------------------------------
__device__ __forceinline__ uint32_t smem_u32(const void* p) {
    uint32_t a;
    asm("{ .reg .u64 t; cvta.to.shared.u64 t, %1; cvt.u32.u64 %0, t; }" : "=r"(a) : "l"(p));
    return a;
}
#define CP16(dst, src) asm volatile("cp.async.ca.shared.global [%0], [%1], 16;" :: "r"(dst), "l"(src))
#define CPCOMMIT()     asm volatile("cp.async.commit_group;" ::: "memory")
#define CPWAIT0()      asm volatile("cp.async.wait_group 0;" ::: "memory")

__device__ __forceinline__ void ldsm4(uint32_t* r, uint32_t a) {
    asm volatile("ldmatrix.sync.aligned.m8n8.x4.shared.b16 {%0,%1,%2,%3}, [%4];"
                 : "=r"(r[0]), "=r"(r[1]), "=r"(r[2]), "=r"(r[3]) : "r"(a));
}
__device__ __forceinline__ void mma16816(float* d, const uint32_t* a, const uint32_t* b) {
    asm volatile("mma.sync.aligned.m16n8k16.row.col.f32.f16.f16.f32 "
                 "{%0,%1,%2,%3},{%4,%5,%6,%7},{%8,%9},{%0,%1,%2,%3};"
                 : "+f"(d[0]), "+f"(d[1]), "+f"(d[2]), "+f"(d[3])
                 : "r"(a[0]), "r"(a[1]), "r"(a[2]), "r"(a[3]), "r"(b[0]), "r"(b[1]));
}

__device__ __forceinline__ uint32_t pack2(uint16_t a, uint16_t b) {
    return (uint32_t)a | ((uint32_t)b << 16);
}
__device__ __forceinline__ uint32_t pcvt2(float x, float y) {
    return pack2(__half_as_ushort(__float2half_rn(x)),
                 __half_as_ushort(__float2half_rn(y)));
}

// ---------------------------------------------------------------------------
// Fused weight transpose + convert (z selects which W):  T[n][k] = fp16(W[k][n])
// ---------------------------------------------------------------------------
__global__ __launch_bounds__(256) void wsplit_kernel(
    const float* __restrict__ W0, const float* __restrict__ W1,
    const float* __restrict__ W2, const float* __restrict__ W3,
    __half* __restrict__ T0, __half* __restrict__ T1,
    __half* __restrict__ T2, __half* __restrict__ T3)
{
    const int z = blockIdx.z;
    const float* W = (z == 0) ? W0 : (z == 1) ? W1 : (z == 2) ? W2 : W3;
    __half* Th     = (z == 0) ? T0 : (z == 1) ? T1 : (z == 2) ? T2 : T3;

    __shared__ float ts[32][33];
    const int tid = threadIdx.x;
    const int tx = tid & 31, ty = tid >> 5;
    const int k0 = blockIdx.x * 32, n0 = blockIdx.y * 32;
#pragma unroll
    for (int p = 0; p < 4; p++)
        ts[ty + 8 * p][tx] = W[(size_t)(k0 + ty + 8 * p) * DM + n0 + tx];
    __syncthreads();
#pragma unroll
    for (int p = 0; p < 4; p++) {
        const int r = ty + 8 * p;
        Th[(size_t)(n0 + r) * DM + k0 + tx] = __float2half_rn(ts[tx][r]);
    }
}

// ---------------------------------------------------------------------------
// Fused QKV GEMM: K macro-chunk 64 (4 k16 steps per sync), 144B-stride stages.
// A (fp32) staged in two 32-col register halves per macro-chunk.
// ---------------------------------------------------------------------------
#define Q_ST 18432              // stage: 128 rows x 144B
#define G_SMEM (4 * Q_ST)       // 73728 (also >= 128*136*2 V-bounce)
#define TPAD 136

__global__ __launch_bounds__(256, 2) void gemm_qkv_kernel(
    const float* __restrict__ A0, const float* __restrict__ A1,
    const float* __restrict__ A2,
    const __half* __restrict__ B0, const __half* __restrict__ B1,
    const __half* __restrict__ B2,
    const float* __restrict__ bias0, const float* __restrict__ bias1,
    const float* __restrict__ bias2,
    __half* __restrict__ O0, __half* __restrict__ O1, __half* __restrict__ O2)
{
    extern __shared__ char smc[];
    const uint32_t smb = smem_u32(smc);
    const int z = blockIdx.z;
    const float*  A    = (z == 0) ? A0 : (z == 1) ? A1 : A2;
    const __half* Bh   = (z == 0) ? B0 : (z == 1) ? B1 : B2;
    const float*  bias = (z == 0) ? bias0 : (z == 1) ? bias1 : bias2;
    __half* Oh         = (z == 0) ? O0 : (z == 1) ? O1 : O2;

    const int tid = threadIdx.x, lane = tid & 31, wid = tid >> 5;
    const int m0 = blockIdx.y * 128, n0 = blockIdx.x * 128;
    const int wm = (wid >> 2) * 64, wn = (wid & 3) * 32;
    const uint32_t SAH = smb, SBH = smb + 2 * Q_ST;

    const int r0a = tid >> 2, c0a = tid & 3;   // A loader: 64 rows x 4x8 fp32 cols

    // prologue: A chunk0 half0 -> regs; B chunk0 (64 k-cols) -> cp.async
    float4 areg[2][2];
#pragma unroll
    for (int p = 0; p < 2; p++) {
        const float* src = A + (size_t)(m0 + r0a + p * 64) * DM + c0a * 8;
        areg[p][0] = ((const float4*)src)[0];
        areg[p][1] = ((const float4*)src)[1];
    }
#pragma unroll
    for (int p = 0; p < 4; p++) {
        const int idx = tid + p * 256, r = idx >> 3, c = idx & 7;
        CP16(SBH + (uint32_t)r * 144u + (uint32_t)c * 16u,
             Bh + (size_t)(n0 + r) * DM + c * 8);
    }
    CPCOMMIT();

    float acc[4][4][4];
#pragma unroll
    for (int a = 0; a < 4; a++)
#pragma unroll
        for (int b = 0; b < 4; b++)
#pragma unroll
            for (int c = 0; c < 4; c++) acc[a][b][c] = 0.f;

    for (int ch = 0; ch < 16; ch++) {
        const uint32_t so = (uint32_t)(ch & 1) * Q_ST;
        // store A half0 (cols 0-31 of this macro-chunk)
#pragma unroll
        for (int p = 0; p < 2; p++) {
            uint4 v;
            v.x = pcvt2(areg[p][0].x, areg[p][0].y);
            v.y = pcvt2(areg[p][0].z, areg[p][0].w);
            v.z = pcvt2(areg[p][1].x, areg[p][1].y);
            v.w = pcvt2(areg[p][1].z, areg[p][1].w);
            *(uint4*)(smc + (uint32_t)(r0a + p * 64) * 144u +
                      (uint32_t)c0a * 16u + so) = v;
        }
        // load + store A half1 (cols 32-63)
        {
            const int k0 = ch * 64 + 32;
#pragma unroll
            for (int p = 0; p < 2; p++) {
                const float* src = A + (size_t)(m0 + r0a + p * 64) * DM + k0 + c0a * 8;
                areg[p][0] = ((const float4*)src)[0];
                areg[p][1] = ((const float4*)src)[1];
            }
#pragma unroll
            for (int p = 0; p < 2; p++) {
                uint4 v;
                v.x = pcvt2(areg[p][0].x, areg[p][0].y);
                v.y = pcvt2(areg[p][0].z, areg[p][0].w);
                v.z = pcvt2(areg[p][1].x, areg[p][1].y);
                v.w = pcvt2(areg[p][1].z, areg[p][1].w);
                *(uint4*)(smc + (uint32_t)(r0a + p * 64) * 144u + 64u +
                          (uint32_t)c0a * 16u + so) = v;
            }
        }
        CPWAIT0();
        __syncthreads();
        if (ch + 1 < 16) {
            const int k0 = (ch + 1) * 64;
            const uint32_t sn = (uint32_t)((ch + 1) & 1) * Q_ST;
#pragma unroll
            for (int p = 0; p < 4; p++) {
                const int idx = tid + p * 256, r = idx >> 3, c = idx & 7;
                CP16(SBH + (uint32_t)r * 144u + (uint32_t)c * 16u + sn,
                     Bh + (size_t)(n0 + r) * DM + k0 + c * 8);
            }
            CPCOMMIT();
#pragma unroll
            for (int p = 0; p < 2; p++) {
                const float* src = A + (size_t)(m0 + r0a + p * 64) * DM + k0 + c0a * 8;
                areg[p][0] = ((const float4*)src)[0];
                areg[p][1] = ((const float4*)src)[1];
            }
        }
#pragma unroll
        for (int ks = 0; ks < 4; ks++) {
            uint32_t ah[4][4], bh[4][2];
            const uint32_t aoff = (uint32_t)((lane & 15) * 144 +
                                  (ks * 16 + (lane >> 4) * 8) * 2) + so;
#pragma unroll
            for (int mb = 0; mb < 4; mb++)
                ldsm4(ah[mb], SAH + (uint32_t)(wm + mb * 16) * 144u + aoff);
            const uint32_t boff = (uint32_t)(((lane >> 4) & 1) * 8 * 144 +
                                  (lane & 7) * 144 +
                                  (ks * 16 + ((lane >> 3) & 1) * 8) * 2) + so;
#pragma unroll
            for (int nbp = 0; nbp < 2; nbp++) {
                uint32_t t[4];
                ldsm4(t, SBH + (uint32_t)(wn + nbp * 16) * 144u + boff);
                bh[2 * nbp][0] = t[0];     bh[2 * nbp][1] = t[1];
                bh[2 * nbp + 1][0] = t[2]; bh[2 * nbp + 1][1] = t[3];
            }
#pragma unroll
            for (int mb = 0; mb < 4; mb++)
#pragma unroll
                for (int nb = 0; nb < 4; nb++)
                    mma16816(acc[mb][nb], ah[mb], bh[nb]);
        }
    }
    __syncthreads();

    const int lr = lane >> 2, lc = (lane & 3) * 2;
    if (z != 2) {
        const float sc = (z == 0) ? 0.125f : 1.0f;
#pragma unroll
        for (int mb = 0; mb < 4; mb++) {
#pragma unroll
            for (int nb = 0; nb < 4; nb++) {
                const int col = n0 + wn + nb * 8 + lc;
                const float b0 = bias[col], b1 = bias[col + 1];
#pragma unroll
                for (int half_ = 0; half_ < 2; half_++) {
                    const int row = m0 + wm + mb * 16 + lr + 8 * half_;
                    const float v0 = (acc[mb][nb][2 * half_] + b0) * sc;
                    const float v1 = (acc[mb][nb][2 * half_ + 1] + b1) * sc;
                    const int bb = row >> 11, ss = row & (S_LEN - 1);
                    const int h = col >> 6, d = col & 63;
                    const size_t base = (((size_t)(bb * NH + h) * S_LEN + ss) << 6) + d;
                    *(uint32_t*)(Oh + base) = pcvt2(v0, v1);
                }
            }
        }
    } else {
        __half* tsm = (__half*)smc;
#pragma unroll
        for (int mb = 0; mb < 4; mb++) {
#pragma unroll
            for (int nb = 0; nb < 4; nb++) {
                const int col = wn + nb * 8 + lc;
                const float b0 = bias[n0 + col], b1 = bias[n0 + col + 1];
#pragma unroll
                for (int half_ = 0; half_ < 2; half_++) {
                    const int row = wm + mb * 16 + lr + 8 * half_;
                    tsm[(size_t)col * TPAD + row] =
                        __float2half_rn(acc[mb][nb][2 * half_] + b0);
                    tsm[(size_t)(col + 1) * TPAD + row] =
                        __float2half_rn(acc[mb][nb][2 * half_ + 1] + b1);
                }
            }
        }
        __syncthreads();
        const int dl = tid >> 1;
        const int tof = (tid & 1) * 64;
        const int bb = m0 >> 11, ss0 = (m0 & (S_LEN - 1)) + tof;
        const int n = n0 + dl, h = n >> 6, d = n & 63;
        __half* dst = Oh + ((size_t)(bb * NH + h) * DK + d) * S_LEN + ss0;
        const __half* srcr = tsm + (size_t)dl * TPAD + tof;
#pragma unroll
        for (int j = 0; j < 8; j++)
            ((uint4*)dst)[j] = ((const uint4*)srcr)[j];
    }
}

// ---------------------------------------------------------------------------
// Output projection GEMM (unchanged from R13): macro-chunk 64, 144B rows.
// ---------------------------------------------------------------------------
#define O_ST 18432
#define O_SMEM (4 * O_ST)

__global__ __launch_bounds__(256, 2) void gemm_o_kernel(
    const __half* __restrict__ Ah, const __half* __restrict__ Bh,
    const float* __restrict__ bias, float* __restrict__ Of)
{
    extern __shared__ char smc[];
    const uint32_t smb = smem_u32(smc);
    const int tid = threadIdx.x, lane = tid & 31, wid = tid >> 5;
    const int m0 = blockIdx.y * 128, n0 = blockIdx.x * 128;
    const int wm = (wid >> 2) * 64, wn = (wid & 3) * 32;
    const uint32_t SAH = smb, SBH = smb + 2 * O_ST;

#pragma unroll
    for (int p = 0; p < 4; p++) {
        const int idx = tid + p * 256, r = idx >> 3, c = idx & 7;
        const uint32_t d = (uint32_t)r * 144u + (uint32_t)c * 16u;
        CP16(SAH + d, Ah + (size_t)(m0 + r) * DM + c * 8);
        CP16(SBH + d, Bh + (size_t)(n0 + r) * DM + c * 8);
    }
    CPCOMMIT();

    float acc[4][4][4];
#pragma unroll
    for (int a = 0; a < 4; a++)
#pragma unroll
        for (int b = 0; b < 4; b++)
#pragma unroll
            for (int c = 0; c < 4; c++) acc[a][b][c] = 0.f;

    CPWAIT0();
    __syncthreads();

    for (int ch = 0; ch < 16; ch++) {
        if (ch > 0) { CPWAIT0(); __syncthreads(); }
        if (ch + 1 < 16) {
            const int k0 = (ch + 1) * 64;
            const uint32_t sn = (uint32_t)((ch + 1) & 1) * O_ST;
#pragma unroll
            for (int p = 0; p < 4; p++) {
                const int idx = tid + p * 256, r = idx >> 3, c = idx & 7;
                const uint32_t d = (uint32_t)r * 144u + (uint32_t)c * 16u + sn;
                CP16(SAH + d, Ah + (size_t)(m0 + r) * DM + k0 + c * 8);
                CP16(SBH + d, Bh + (size_t)(n0 + r) * DM + k0 + c * 8);
            }
            CPCOMMIT();
        }
        const uint32_t so = (uint32_t)(ch & 1) * O_ST;
#pragma unroll
        for (int ks = 0; ks < 4; ks++) {
            uint32_t ah[4][4], bh[4][2];
            const uint32_t aoff = (uint32_t)((lane & 15) * 144 +
                                  (ks * 16 + (lane >> 4) * 8) * 2) + so;
#pragma unroll
            for (int mb = 0; mb < 4; mb++)
                ldsm4(ah[mb], SAH + (uint32_t)(wm + mb * 16) * 144u + aoff);
            const uint32_t boff = (uint32_t)(((lane >> 4) & 1) * 8 * 144 +
                                  (lane & 7) * 144 +
                                  (ks * 16 + ((lane >> 3) & 1) * 8) * 2) + so;
#pragma unroll
            for (int nbp = 0; nbp < 2; nbp++) {
                uint32_t t[4];
                ldsm4(t, SBH + (uint32_t)(wn + nbp * 16) * 144u + boff);
                bh[2 * nbp][0] = t[0];     bh[2 * nbp][1] = t[1];
                bh[2 * nbp + 1][0] = t[2]; bh[2 * nbp + 1][1] = t[3];
            }
#pragma unroll
            for (int mb = 0; mb < 4; mb++)
#pragma unroll
                for (int nb = 0; nb < 4; nb++)
                    mma16816(acc[mb][nb], ah[mb], bh[nb]);
        }
    }

    const int lr = lane >> 2, lc = (lane & 3) * 2;
#pragma unroll
    for (int mb = 0; mb < 4; mb++) {
#pragma unroll
        for (int nb = 0; nb < 4; nb++) {
            const int col = n0 + wn + nb * 8 + lc;
            const float b0 = bias[col], b1 = bias[col + 1];
#pragma unroll
            for (int half_ = 0; half_ < 2; half_++) {
                const int row = m0 + wm + mb * 16 + lr + 8 * half_;
                *(float2*)(Of + (size_t)row * DM + col) =
                    make_float2(acc[mb][nb][2 * half_] + b0,
                                acc[mb][nb][2 * half_ + 1] + b1);
            }
        }
    }
}

// ---------------------------------------------------------------------------
// Flash attention (unchanged from R13): KV macro-chunk 128, Q frags hoisted.
// ---------------------------------------------------------------------------
#define AK_ST 18432
#define AV_ST 17408
#define A_QB  18432
#define A_SMEM (A_QB + 2 * AK_ST + 2 * AV_ST)

__global__ __launch_bounds__(256, 2) void attn_mma_kernel(
    const __half* __restrict__ Qh, const __half* __restrict__ Kh,
    const __half* __restrict__ Vth, __half* __restrict__ AO)
{
    extern __shared__ char smc[];
    const uint32_t smb = smem_u32(smc);
    const int tid = threadIdx.x, lane = tid & 31, wid = tid >> 5;
    const int bh = blockIdx.y;
    const int q0 = blockIdx.x * 128;
    const uint32_t SQH = smb;
    const uint32_t SKH = smb + A_QB, SVH = SKH + 2 * AK_ST;

    const size_t qbase = ((size_t)bh * S_LEN + q0) * DK;
    const size_t kbase = (size_t)bh * S_LEN * DK;
    const size_t vbase = (size_t)bh * DK * S_LEN;

    {
#pragma unroll
        for (int p = 0; p < 4; p++) {
            const int idx = tid + p * 256, r = idx >> 3, c = idx & 7;
            CP16(SQH + (uint32_t)r * 144u + (uint32_t)c * 16u,
                 Qh + qbase + (size_t)r * DK + c * 8);
            CP16(SKH + (uint32_t)r * 144u + (uint32_t)c * 16u,
                 Kh + kbase + (size_t)r * DK + c * 8);
        }
#pragma unroll
        for (int p = 0; p < 4; p++) {
            const int idx = tid + p * 256, r = idx >> 4, c = idx & 15;
            CP16(SVH + (uint32_t)r * 272u + (uint32_t)c * 16u,
                 Vth + vbase + (size_t)r * S_LEN + c * 8);
        }
        CPCOMMIT();
    }

    const int r0 = wid * 16;
    float oacc[8][4];
    float lsum[2] = {0.f, 0.f};
#pragma unroll
    for (int db = 0; db < 8; db++)
#pragma unroll
        for (int e = 0; e < 4; e++) oacc[db][e] = 0.f;

    CPWAIT0();
    __syncthreads();

    uint32_t qf_all[4][4];
#pragma unroll
    for (int ks = 0; ks < 4; ks++)
        ldsm4(qf_all[ks], SQH + (uint32_t)((r0 + (lane & 15)) * 144 +
                                           (ks * 16 + (lane >> 4) * 8) * 2));

    for (int i = 0; i < 16; i++) {
        if (i > 0) { CPWAIT0(); __syncthreads(); }
        if (i + 1 < 16) {
            const int t0 = (i + 1) * 128;
            const uint32_t skn = (uint32_t)((i + 1) & 1) * AK_ST;
            const uint32_t svn = (uint32_t)((i + 1) & 1) * AV_ST;
#pragma unroll
            for (int p = 0; p < 4; p++) {
                const int idx = tid + p * 256, r = idx >> 3, c = idx & 7;
                CP16(SKH + (uint32_t)r * 144u + (uint32_t)c * 16u + skn,
                     Kh + kbase + (size_t)(t0 + r) * DK + c * 8);
            }
#pragma unroll
            for (int p = 0; p < 4; p++) {
                const int idx = tid + p * 256, r = idx >> 4, c = idx & 15;
                CP16(SVH + (uint32_t)r * 272u + (uint32_t)c * 16u + svn,
                     Vth + vbase + (size_t)r * S_LEN + t0 + c * 8);
            }
            CPCOMMIT();
        }
        const uint32_t sk = (uint32_t)(i & 1) * AK_ST;
        const uint32_t sv = (uint32_t)(i & 1) * AV_ST;

#pragma unroll
        for (int hf = 0; hf < 2; hf++) {
            float sacc[8][4];
#pragma unroll
            for (int nb = 0; nb < 8; nb++)
#pragma unroll
                for (int e = 0; e < 4; e++) sacc[nb][e] = 0.f;
            const uint32_t kbs = SKH + sk + (uint32_t)(hf * 64) * 144u;
#pragma unroll
            for (int ks = 0; ks < 4; ks++) {
                const uint32_t bo = (uint32_t)(((lane >> 4) & 1) * 8 * 144 +
                                     (lane & 7) * 144 +
                                     (ks * 16 + ((lane >> 3) & 1) * 8) * 2);
#pragma unroll
                for (int nbp = 0; nbp < 4; nbp++) {
                    uint32_t t[4];
                    ldsm4(t, kbs + (uint32_t)(nbp * 16) * 144u + bo);
                    mma16816(sacc[2 * nbp],     qf_all[ks], t);
                    mma16816(sacc[2 * nbp + 1], qf_all[ks], t + 2);
                }
            }

#pragma unroll
            for (int nb = 0; nb < 8; nb++)
#pragma unroll
                for (int e = 0; e < 4; e++) {
                    const float p = __expf(sacc[nb][e]);
                    lsum[e >> 1] += p;
                    sacc[nb][e] = p;
                }

            const uint32_t vbs = SVH + sv;
#pragma unroll
            for (int ts = 0; ts < 4; ts++) {
                uint32_t ph[4];
                ph[0] = pcvt2(sacc[2 * ts][0],     sacc[2 * ts][1]);
                ph[1] = pcvt2(sacc[2 * ts][2],     sacc[2 * ts][3]);
                ph[2] = pcvt2(sacc[2 * ts + 1][0], sacc[2 * ts + 1][1]);
                ph[3] = pcvt2(sacc[2 * ts + 1][2], sacc[2 * ts + 1][3]);
                const uint32_t vo = (uint32_t)(((lane >> 4) & 1) * 8 * 272 +
                                     (lane & 7) * 272 +
                                     (hf * 64 + ts * 16 + ((lane >> 3) & 1) * 8) * 2);
#pragma unroll
                for (int dbp = 0; dbp < 4; dbp++) {
                    uint32_t t[4];
                    ldsm4(t, vbs + (uint32_t)(dbp * 16) * 272u + vo);
                    mma16816(oacc[2 * dbp],     ph, t);
                    mma16816(oacc[2 * dbp + 1], ph, t + 2);
                }
            }
        }
    }

#pragma unroll
    for (int e = 0; e < 2; e++) {
        lsum[e] += __shfl_xor_sync(0xffffffffu, lsum[e], 1);
        lsum[e] += __shfl_xor_sync(0xffffffffu, lsum[e], 2);
    }
    const float inv0 = 1.f / lsum[0], inv1 = 1.f / lsum[1];

    const int bb = bh >> 4, hh = bh & 15;
    const int rowa = q0 + r0 + (lane >> 2);
#pragma unroll
    for (int db = 0; db < 8; db++) {
        const int col = hh * 64 + db * 8 + (lane & 3) * 2;
        const size_t ba = ((size_t)bb * S_LEN + rowa) * DM + col;
        const size_t bb2 = ba + (size_t)8 * DM;
        *(uint32_t*)(AO + ba)  = pcvt2(oacc[db][0] * inv0, oacc[db][1] * inv0);
        *(uint32_t*)(AO + bb2) = pcvt2(oacc[db][2] * inv1, oacc[db][3] * inv1);
    }
}

// ---------------------------------------------------------------------------
extern "C" void kernel_launch(void* const* d_in, const int* in_sizes, int n_in,
                              void* d_out, int out_size)
{
    const float* q  = (const float*)d_in[0];
    const float* k  = (const float*)d_in[1];
    const float* v  = (const float*)d_in[2];
    const float* Wq = (const float*)d_in[3];
    const float* bq = (const float*)d_in[4];
    const float* Wk = (const float*)d_in[5];
    const float* bk = (const float*)d_in[6];
    const float* Wv = (const float*)d_in[7];
    const float* bv = (const float*)d_in[8];
    const float* Wo = (const float*)d_in[9];
    const float* bo = (const float*)d_in[10];
    float* out = (float*)d_out;

    __half *qh, *kh, *vt, *at, *wq, *wk, *wv, *wo;
    cudaGetSymbolAddress((void**)&qh, g_q);
    cudaGetSymbolAddress((void**)&kh, g_k);
    cudaGetSymbolAddress((void**)&vt, g_vt);
    cudaGetSymbolAddress((void**)&at, g_at);
    cudaGetSymbolAddress((void**)&wq, g_wq);
    cudaGetSymbolAddress((void**)&wk, g_wk);
    cudaGetSymbolAddress((void**)&wv, g_wv);
    cudaGetSymbolAddress((void**)&wo, g_wo);

    cudaFuncSetAttribute(gemm_qkv_kernel, cudaFuncAttributeMaxDynamicSharedMemorySize, G_SMEM);
    cudaFuncSetAttribute(gemm_o_kernel, cudaFuncAttributeMaxDynamicSharedMemorySize, O_SMEM);
    cudaFuncSetAttribute(attn_mma_kernel, cudaFuncAttributeMaxDynamicSharedMemorySize, A_SMEM);

    dim3 wg(32, 32, 4);
    wsplit_kernel<<<wg, 256>>>(Wq, Wk, Wv, Wo, wq, wk, wv, wo);

    dim3 gqkv(DM / 128, MROWS / 128, 3);
    gemm_qkv_kernel<<<gqkv, 256, G_SMEM>>>(q, k, v, wq, wk, wv, bq, bk, bv,
                                           qh, kh, vt);

    dim3 ga(S_LEN / 128, NB * NH);
    attn_mma_kernel<<<ga, 256, A_SMEM>>>(qh, kh, vt, at);

    dim3 gg(DM / 128, MROWS / 128);
    gemm_o_kernel<<<gg, 256, O_SMEM>>>(at, wo, bo, out);
}